// round 3
// baseline (speedup 1.0000x reference)
#include <cuda_runtime.h>
#include <cuda_fp16.h>
#include <math.h>

#define NN 50000
#define EE 800000
#define BB 64
#define DD 64
#define HHD 2          // heads
#define GG 50
#define HIDN 128
#define HD 128         // H*D
#define LLAYERS 3
#define TBL 8192       // table resolution over [0, 8)
#define TBL_SCALE 1024.0f   // TBL / 8.0

// ---- scratch (static device arrays; no allocation allowed) ----
__device__ float  g_x[NN * DD];
__device__ float  g_h[NN * HD];
__device__ float  g_el[NN * HHD];
__device__ float  g_er[NN * HHD];
__device__ int    g_deg[NN];
__device__ int    g_rowptr[NN + 1];
__device__ int    g_wpos[NN];
__device__ int    g_esrc[EE];
__device__ int    g_edst[EE];
__device__ float2 g_mif[EE];     // {f, bitcast(i)} per sorted slot
__device__ float2 g_exP[EE];     // {ex0, ex1} per sorted slot (per layer)
__device__ __half2 g_T2[(TBL + 1) * HD];  // pair-packed w(r)*C(r) table

__device__ __forceinline__ float ssp(float x) {
    return fmaxf(x, 0.f) + log1pf(expf(-fabsf(x))) - 0.69314718055994531f;
}

// ---------------- CSR build ----------------
__global__ void zero_deg() {
    int i = blockIdx.x * blockDim.x + threadIdx.x;
    if (i < NN) g_deg[i] = 0;
}

__global__ void count_deg(const int* __restrict__ dst) {
    int e = blockIdx.x * blockDim.x + threadIdx.x;
    if (e < EE) atomicAdd(&g_deg[dst[e]], 1);
}

__global__ void scan_kernel() {   // 1 block, 1024 threads
    __shared__ int sh[1024];
    __shared__ int carry_s;
    int t = threadIdx.x;
    if (t == 0) carry_s = 0;
    __syncthreads();
    for (int base = 0; base < NN; base += 1024) {
        int idx = base + t;
        int v = (idx < NN) ? g_deg[idx] : 0;
        sh[t] = v;
        __syncthreads();
#pragma unroll
        for (int o = 1; o < 1024; o <<= 1) {
            int x = (t >= o) ? sh[t - o] : 0;
            __syncthreads();
            sh[t] += x;
            __syncthreads();
        }
        int c = carry_s;
        if (idx < NN) {
            int excl = c + sh[t] - v;
            g_rowptr[idx] = excl;
            g_wpos[idx] = excl;
        }
        __syncthreads();
        if (t == 1023) carry_s = c + sh[1023];
        __syncthreads();
    }
    if (t == 0) g_rowptr[NN] = carry_s;
}

__global__ void scatter_kernel(const float* __restrict__ R,
                               const int* __restrict__ src,
                               const int* __restrict__ dst) {
    int e = blockIdx.x * blockDim.x + threadIdx.x;
    if (e >= EE) return;
    int s = src[e], d = dst[e];
    float dx = R[s * 3 + 0] - R[d * 3 + 0];
    float dy = R[s * 3 + 1] - R[d * 3 + 1];
    float dz = R[s * 3 + 2] - R[d * 3 + 2];
    float r = sqrtf(dx * dx + dy * dy + dz * dz);
    int pos = atomicAdd(&g_wpos[d], 1);
    g_esrc[pos] = s;
    g_edst[pos] = d;
    int i; float f;
    if (r < 8.0f) {
        float u = r * TBL_SCALE;
        i = (int)u;
        f = u - (float)i;
    } else {
        i = TBL; f = 0.0f;   // zero row
    }
    g_mif[pos] = make_float2(f, __int_as_float(i));
}

// ---------------- embedding gather ----------------
__global__ void embed_kernel(const int* __restrict__ Z,
                             const float* __restrict__ emb) {
    int i = blockIdx.x * blockDim.x + threadIdx.x;
    if (i >= NN * DD) return;
    int n = i >> 6, d = i & 63;
    g_x[i] = emb[Z[n] * DD + d];
}

// ---------------- per-node: h = x @ fc_w, el/er attention logits ----------------
__global__ void node_pre(const float* __restrict__ fcw,
                         const float* __restrict__ al,
                         const float* __restrict__ ar) {
    int n = blockIdx.x;
    int t = threadIdx.x;  // 128 threads
    __shared__ float xs[DD];
    __shared__ float red_l[HHD];
    __shared__ float red_r[HHD];
    if (t < DD) xs[t] = g_x[n * DD + t];
    if (t < HHD) { red_l[t] = 0.f; red_r[t] = 0.f; }
    __syncthreads();
    float acc = 0.f;
#pragma unroll
    for (int k = 0; k < DD; k++) acc = fmaf(xs[k], fcw[k * HD + t], acc);
    g_h[n * HD + t] = acc;
    int head = t >> 6, d = t & 63;
    float pl = acc * al[head * DD + d];
    float pr = acc * ar[head * DD + d];
#pragma unroll
    for (int o = 16; o > 0; o >>= 1) {
        pl += __shfl_down_sync(0xffffffffu, pl, o);
        pr += __shfl_down_sync(0xffffffffu, pr, o);
    }
    if ((t & 31) == 0) { atomicAdd(&red_l[head], pl); atomicAdd(&red_r[head], pr); }
    __syncthreads();
    if (t < HHD) { g_el[n * HHD + t] = red_l[t]; g_er[n * HHD + t] = red_r[t]; }
}

// ---------------- build fp16 pair-packed w(r)*C(r) table ----------------
__global__ void build_table(const float* __restrict__ off,
                            const float* __restrict__ wid,
                            const float* __restrict__ w1,
                            const float* __restrict__ b1,
                            const float* __restrict__ w2,
                            const float* __restrict__ b2) {
    int i = blockIdx.x;       // 0..TBL
    int t = threadIdx.x;      // 128 threads
    __shared__ float gs[2][GG];
    __shared__ float hid[2][HIDN];
    float v01[2];
#pragma unroll
    for (int q = 0; q < 2; q++) {
        float r = (float)(i + q) * (8.0f / (float)TBL);
        if (t < GG) {
            float w = wid[t];
            float coef = -0.5f / (w * w);
            float dr = r - off[t];
            gs[q][t] = expf(coef * dr * dr);
        }
    }
    __syncthreads();
#pragma unroll
    for (int q = 0; q < 2; q++) {
        float acc = b1[t];
#pragma unroll
        for (int g = 0; g < GG; g++) acc = fmaf(gs[q][g], w1[g * HD + t], acc);
        hid[q][t] = ssp(acc);
    }
    __syncthreads();
#pragma unroll
    for (int q = 0; q < 2; q++) {
        float acc2 = b2[t];
#pragma unroll 8
        for (int k = 0; k < HIDN; k++) acc2 = fmaf(hid[q][k], w2[k * HD + t], acc2);
        float r = (float)(i + q) * (8.0f / (float)TBL);
        float C = (r < 8.0f) ? 0.5f * (cosf(r * 0.39269908169872414f) + 1.0f) : 0.0f;
        v01[q] = acc2 * C;
    }
    if (i == TBL) { v01[0] = 0.f; v01[1] = 0.f; }  // skip row
    g_T2[i * HD + t] = __floats2half2_rn(v01[0], v01[1]);
}

// ---------------- per-edge softmax numerators (pos-ordered) ----------------
__global__ void edge_ex() {
    int pos = blockIdx.x * blockDim.x + threadIdx.x;
    if (pos >= EE) return;
    int s = g_esrc[pos];
    int d = g_edst[pos];
    float ev0 = g_el[s * 2 + 0] + g_er[d * 2 + 0];
    float ev1 = g_el[s * 2 + 1] + g_er[d * 2 + 1];
    ev0 = ev0 > 0.f ? ev0 : 0.2f * ev0;
    ev1 = ev1 > 0.f ? ev1 : 0.2f * ev1;
    g_exP[pos] = make_float2(expf(ev0), expf(ev1));  // shift-invariant softmax
}

// ---------------- fused gather + normalize + node MLP + residual ----------------
__global__ void __launch_bounds__(128) gather_update(const float* __restrict__ m1,
                                                     const float* __restrict__ mb1,
                                                     const float* __restrict__ m2,
                                                     const float* __restrict__ mb2) {
    int n = blockIdx.x;
    int t = threadIdx.x;  // 128 threads, one feature each
    int beg = g_rowptr[n];
    int end = g_rowptr[n + 1];
    float acc = 0.f;
    float exs = 0.f;
    for (int pos = beg; pos < end; pos++) {
        float2 ex = g_exP[pos];
        float2 mif = g_mif[pos];
        int s = g_esrc[pos];
        int i = __float_as_int(mif.y);
        float f = mif.x;
        __half2 tv = g_T2[i * HD + t];
        float2 tf = __half22float2(tv);
        float w = fmaf(f, tf.y - tf.x, tf.x);
        float h = g_h[s * HD + t];
        float exh = (t < 64) ? ex.x : ex.y;
        acc = fmaf(h * w, exh, acc);
        exs += exh;
    }
    float a = (exs > 0.f) ? acc / exs : 0.f;
    __shared__ float v[HD];
    __shared__ float t1[DD];
    v[t] = ssp(a);
    __syncthreads();
    if (t < DD) {
        float ac = mb1[t];
#pragma unroll 8
        for (int k = 0; k < HD; k++) ac = fmaf(v[k], m1[k * DD + t], ac);
        t1[t] = ssp(ac);
    }
    __syncthreads();
    if (t < DD) {
        float ac2 = mb2[t];
#pragma unroll
        for (int k = 0; k < DD; k++) ac2 = fmaf(t1[k], m2[k * DD + t], ac2);
        g_x[n * DD + t] += ac2;
    }
}

// ---------------- output head ----------------
__global__ void zero_out(float* out) {
    if (threadIdx.x < BB) out[threadIdx.x] = 0.f;
}

__global__ void out_kernel(const float* __restrict__ w1,
                           const float* __restrict__ b1,
                           const float* __restrict__ w2,
                           const float* __restrict__ b2,
                           const int* __restrict__ gid,
                           float* __restrict__ out) {
    int n = blockIdx.x;
    int t = threadIdx.x;  // 128 threads
    __shared__ float xs[DD];
    __shared__ float red[4];
    if (t < DD) xs[t] = g_x[n * DD + t];
    __syncthreads();
    float acc = b1[t];
#pragma unroll
    for (int k = 0; k < DD; k++) acc = fmaf(xs[k], w1[k * 128 + t], acc);
    float p = ssp(acc) * w2[t];
#pragma unroll
    for (int o = 16; o > 0; o >>= 1) p += __shfl_down_sync(0xffffffffu, p, o);
    if ((t & 31) == 0) red[t >> 5] = p;
    __syncthreads();
    if (t == 0) {
        float hh = red[0] + red[1] + red[2] + red[3] + b2[0];
        atomicAdd(&out[gid[n]], hh);
    }
}

extern "C" void kernel_launch(void* const* d_in, const int* in_sizes, int n_in,
                              void* d_out, int out_size) {
    const float* R    = (const float*)d_in[0];
    const int*   Z    = (const int*)d_in[1];
    const int*   src  = (const int*)d_in[2];
    const int*   dst  = (const int*)d_in[3];
    const int*   gid  = (const int*)d_in[4];
    const float* emb  = (const float*)d_in[5];
    const float* off  = (const float*)d_in[6];
    const float* wid  = (const float*)d_in[7];
    const float* fcw  = (const float*)d_in[8];
    const float* al   = (const float*)d_in[9];
    const float* ar   = (const float*)d_in[10];
    const float* fw1  = (const float*)d_in[11];
    const float* fb1  = (const float*)d_in[12];
    const float* fw2  = (const float*)d_in[13];
    const float* fb2  = (const float*)d_in[14];
    const float* m1   = (const float*)d_in[15];
    const float* mb1  = (const float*)d_in[16];
    const float* m2   = (const float*)d_in[17];
    const float* mb2  = (const float*)d_in[18];
    const float* ow1  = (const float*)d_in[19];
    const float* ob1  = (const float*)d_in[20];
    const float* ow2  = (const float*)d_in[21];
    const float* ob2  = (const float*)d_in[22];
    float* out = (float*)d_out;

    // CSR build (per launch; deterministic up to fp sum order)
    zero_deg<<<(NN + 255) / 256, 256>>>();
    count_deg<<<(EE + 255) / 256, 256>>>(dst);
    scan_kernel<<<1, 1024>>>();
    scatter_kernel<<<(EE + 255) / 256, 256>>>(R, src, dst);
    embed_kernel<<<(NN * DD + 255) / 256, 256>>>(Z, emb);

    for (int l = 0; l < LLAYERS; l++) {
        node_pre<<<NN, 128>>>(fcw + l * DD * HD, al + l * HHD * DD, ar + l * HHD * DD);
        build_table<<<TBL + 1, 128>>>(off, wid,
                                      fw1 + l * GG * HD, fb1 + l * HD,
                                      fw2 + l * HIDN * HD, fb2 + l * HD);
        edge_ex<<<(EE + 255) / 256, 256>>>();
        gather_update<<<NN, 128>>>(m1 + l * HD * DD, mb1 + l * DD,
                                   m2 + l * DD * DD, mb2 + l * DD);
    }

    zero_out<<<1, 64>>>(out);
    out_kernel<<<NN, 128>>>(ow1, ob1, ow2, ob2, gid, out);
}

// round 5
// speedup vs baseline: 1.0304x; 1.0304x over previous
#include <cuda_runtime.h>
#include <cuda_fp16.h>
#include <math.h>

#define NN 50000
#define EE 800000
#define BB 64
#define DD 64
#define HHD 2
#define GG 50
#define HIDN 128
#define HD 128
#define LLAYERS 3
#define TBL 8192
#define TBL_SCALE 1024.0f
#define NB 16            // nodes per block in node GEMM kernels

// ---- scratch ----
__device__ float  g_x[NN * DD];
__device__ float  g_h[NN * HD];
__device__ float  g_v[NN * HD];
__device__ float  g_el[NN * HHD];
__device__ float  g_er[NN * HHD];
__device__ int    g_deg[NN];
__device__ int    g_rowptr[NN + 1];
__device__ int    g_wpos[NN];
__device__ float2 g_su[EE];      // {u = r*1024 (or TBL), bitcast(src)}
__device__ int    g_edst[EE];
__device__ float4 g_meta[EE];    // {u, bitcast(src), ex0, ex1}
__device__ __half2 g_T2[(TBL + 1) * HD];

__device__ __forceinline__ float ssp(float x) {
    return fmaxf(x, 0.f) + log1pf(expf(-fabsf(x))) - 0.69314718055994531f;
}

// ---------------- CSR build ----------------
__global__ void zero_deg() {
    int i = blockIdx.x * blockDim.x + threadIdx.x;
    if (i < NN) g_deg[i] = 0;
}

__global__ void count_deg(const int* __restrict__ dst) {
    int e = blockIdx.x * blockDim.x + threadIdx.x;
    if (e < EE) atomicAdd(&g_deg[dst[e]], 1);
}

__global__ void scan_kernel() {
    __shared__ int sh[1024];
    __shared__ int carry_s;
    int t = threadIdx.x;
    if (t == 0) carry_s = 0;
    __syncthreads();
    for (int base = 0; base < NN; base += 1024) {
        int idx = base + t;
        int v = (idx < NN) ? g_deg[idx] : 0;
        sh[t] = v;
        __syncthreads();
#pragma unroll
        for (int o = 1; o < 1024; o <<= 1) {
            int x = (t >= o) ? sh[t - o] : 0;
            __syncthreads();
            sh[t] += x;
            __syncthreads();
        }
        int c = carry_s;
        if (idx < NN) {
            int excl = c + sh[t] - v;
            g_rowptr[idx] = excl;
            g_wpos[idx] = excl;
        }
        __syncthreads();
        if (t == 1023) carry_s = c + sh[1023];
        __syncthreads();
    }
    if (t == 0) g_rowptr[NN] = carry_s;
}

__global__ void scatter_kernel(const float* __restrict__ R,
                               const int* __restrict__ src,
                               const int* __restrict__ dst) {
    int e = blockIdx.x * blockDim.x + threadIdx.x;
    if (e >= EE) return;
    int s = src[e], d = dst[e];
    float dx = R[s * 3 + 0] - R[d * 3 + 0];
    float dy = R[s * 3 + 1] - R[d * 3 + 1];
    float dz = R[s * 3 + 2] - R[d * 3 + 2];
    float r = sqrtf(dx * dx + dy * dy + dz * dz);
    int pos = atomicAdd(&g_wpos[d], 1);
    float u = (r < 8.0f) ? r * TBL_SCALE : (float)TBL;  // TBL row is zeroed
    g_su[pos] = make_float2(u, __int_as_float(s));
    g_edst[pos] = d;
}

// ---------------- embedding gather ----------------
__global__ void embed_kernel(const int* __restrict__ Z,
                             const float* __restrict__ emb) {
    int i = blockIdx.x * blockDim.x + threadIdx.x;
    if (i >= NN * DD) return;
    int n = i >> 6, d = i & 63;
    g_x[i] = emb[Z[n] * DD + d];
}

// ---------------- batched node pre: h = x @ fcw, el/er logits ----------------
// 16 nodes/block, 256 threads. thread: node n = t&15, col group cg = t>>4 (8 cols)
__global__ void __launch_bounds__(256) nodes_pre(const float* __restrict__ fcw,
                                                 const float* __restrict__ al,
                                                 const float* __restrict__ ar) {
    int n0 = blockIdx.x * NB;
    int t = threadIdx.x;
    __shared__ float xs[NB * 65];
    __shared__ float els[NB * 2], ers[NB * 2];
    for (int i = t; i < NB * 64; i += 256)
        xs[(i >> 6) * 65 + (i & 63)] = g_x[n0 * 64 + i];
    if (t < NB * 2) { els[t] = 0.f; ers[t] = 0.f; }
    __syncthreads();
    int n = t & 15, cg = t >> 4;
    float acc[8];
#pragma unroll
    for (int j = 0; j < 8; j++) acc[j] = 0.f;
    const float4* W4 = (const float4*)fcw;
#pragma unroll 4
    for (int k = 0; k < 64; k++) {
        float xv = xs[n * 65 + k];
        float4 wa = W4[k * 32 + cg * 2];
        float4 wb = W4[k * 32 + cg * 2 + 1];
        acc[0] = fmaf(xv, wa.x, acc[0]);
        acc[1] = fmaf(xv, wa.y, acc[1]);
        acc[2] = fmaf(xv, wa.z, acc[2]);
        acc[3] = fmaf(xv, wa.w, acc[3]);
        acc[4] = fmaf(xv, wb.x, acc[4]);
        acc[5] = fmaf(xv, wb.y, acc[5]);
        acc[6] = fmaf(xv, wb.z, acc[6]);
        acc[7] = fmaf(xv, wb.w, acc[7]);
    }
    int ng = n0 + n;
    ((float4*)g_h)[ng * 32 + cg * 2]     = make_float4(acc[0], acc[1], acc[2], acc[3]);
    ((float4*)g_h)[ng * 32 + cg * 2 + 1] = make_float4(acc[4], acc[5], acc[6], acc[7]);
    int head = cg >> 3;
    int ca = (cg * 8) & 63;
    float4 ala = ((const float4*)al)[head * 16 + (ca >> 2)];
    float4 alb = ((const float4*)al)[head * 16 + (ca >> 2) + 1];
    float4 ara = ((const float4*)ar)[head * 16 + (ca >> 2)];
    float4 arb = ((const float4*)ar)[head * 16 + (ca >> 2) + 1];
    float pl = acc[0]*ala.x + acc[1]*ala.y + acc[2]*ala.z + acc[3]*ala.w
             + acc[4]*alb.x + acc[5]*alb.y + acc[6]*alb.z + acc[7]*alb.w;
    float pr = acc[0]*ara.x + acc[1]*ara.y + acc[2]*ara.z + acc[3]*ara.w
             + acc[4]*arb.x + acc[5]*arb.y + acc[6]*arb.z + acc[7]*arb.w;
    atomicAdd(&els[n * 2 + head], pl);
    atomicAdd(&ers[n * 2 + head], pr);
    __syncthreads();
    if (t < NB * 2) {
        g_el[n0 * 2 + t] = els[t];
        g_er[n0 * 2 + t] = ers[t];
    }
}

// ---------------- build fp16 pair-packed table ----------------
__global__ void build_table(const float* __restrict__ off,
                            const float* __restrict__ wid,
                            const float* __restrict__ w1,
                            const float* __restrict__ b1,
                            const float* __restrict__ w2,
                            const float* __restrict__ b2) {
    int i = blockIdx.x;
    int t = threadIdx.x;
    __shared__ float gs[2][GG];
    __shared__ float hid[2][HIDN];
    float v01[2];
#pragma unroll
    for (int q = 0; q < 2; q++) {
        float r = (float)(i + q) * (8.0f / (float)TBL);
        if (t < GG) {
            float w = wid[t];
            float coef = -0.5f / (w * w);
            float dr = r - off[t];
            gs[q][t] = expf(coef * dr * dr);
        }
    }
    __syncthreads();
#pragma unroll
    for (int q = 0; q < 2; q++) {
        float acc = b1[t];
#pragma unroll
        for (int g = 0; g < GG; g++) acc = fmaf(gs[q][g], w1[g * HD + t], acc);
        hid[q][t] = ssp(acc);
    }
    __syncthreads();
#pragma unroll
    for (int q = 0; q < 2; q++) {
        float acc2 = b2[t];
#pragma unroll 8
        for (int k = 0; k < HIDN; k++) acc2 = fmaf(hid[q][k], w2[k * HD + t], acc2);
        float r = (float)(i + q) * (8.0f / (float)TBL);
        float C = (r < 8.0f) ? 0.5f * (cosf(r * 0.39269908169872414f) + 1.0f) : 0.0f;
        v01[q] = acc2 * C;
    }
    if (i == TBL) { v01[0] = 0.f; v01[1] = 0.f; }
    g_T2[i * HD + t] = __floats2half2_rn(v01[0], v01[1]);
}

// ---------------- per-edge meta: {u, src, ex0, ex1} ----------------
__global__ void edge_ex() {
    int pos = blockIdx.x * blockDim.x + threadIdx.x;
    if (pos >= EE) return;
    float2 su = g_su[pos];
    int s = __float_as_int(su.y);
    int d = g_edst[pos];
    float2 el = ((const float2*)g_el)[s];
    float2 er = ((const float2*)g_er)[d];
    float ev0 = el.x + er.x; ev0 = ev0 > 0.f ? ev0 : 0.2f * ev0;
    float ev1 = el.y + er.y; ev1 = ev1 > 0.f ? ev1 : 0.2f * ev1;
    g_meta[pos] = make_float4(su.x, su.y, expf(ev0), expf(ev1));
}

// ---------------- gather: v = ssp(softmax-weighted message sum) ----------------
__global__ void __launch_bounds__(128) gather_v() {
    int n = blockIdx.x;
    int t = threadIdx.x;
    int beg = g_rowptr[n];
    int end = g_rowptr[n + 1];
    float acc = 0.f, exs = 0.f;
    int pos = beg;
#define EDGE(mm) { \
        float u = mm.x; int s = __float_as_int(mm.y); \
        int i = (int)u; float f = u - (float)i; \
        float2 tf = __half22float2(g_T2[i * HD + t]); \
        float w = fmaf(f, tf.y - tf.x, tf.x); \
        float h = g_h[s * HD + t]; \
        float exh = (t < 64) ? mm.z : mm.w; \
        acc = fmaf(h * w, exh, acc); exs += exh; }
    for (; pos + 4 <= end; pos += 4) {
        float4 m0 = g_meta[pos];
        float4 m1 = g_meta[pos + 1];
        float4 m2 = g_meta[pos + 2];
        float4 m3 = g_meta[pos + 3];
        EDGE(m0) EDGE(m1) EDGE(m2) EDGE(m3)
    }
    for (; pos < end; pos++) { float4 m = g_meta[pos]; EDGE(m) }
#undef EDGE
    float a = (exs > 0.f) ? acc / exs : 0.f;
    g_v[n * HD + t] = ssp(a);
}

// ---------------- batched node MLP: x += m2(ssp(m1(v))) ----------------
// 16 nodes/block, 256 threads. thread: node n = t&15, cg = t>>4 (4 cols)
__global__ void __launch_bounds__(256) nodes_mlp(const float* __restrict__ m1,
                                                 const float* __restrict__ mb1,
                                                 const float* __restrict__ m2,
                                                 const float* __restrict__ mb2) {
    int n0 = blockIdx.x * NB;
    int t = threadIdx.x;
    __shared__ float vs[NB * 129];
    __shared__ float t1s[NB * 65];
    for (int i = t; i < NB * 128; i += 256)
        vs[(i >> 7) * 129 + (i & 127)] = g_v[n0 * 128 + i];
    __syncthreads();
    int n = t & 15, cg = t >> 4;
    float a0 = 0.f, a1 = 0.f, a2 = 0.f, a3 = 0.f;
    const float4* M1 = (const float4*)m1;   // [128][16 float4]
#pragma unroll 4
    for (int k = 0; k < 128; k++) {
        float xv = vs[n * 129 + k];
        float4 w = M1[k * 16 + cg];
        a0 = fmaf(xv, w.x, a0);
        a1 = fmaf(xv, w.y, a1);
        a2 = fmaf(xv, w.z, a2);
        a3 = fmaf(xv, w.w, a3);
    }
    float4 b14 = ((const float4*)mb1)[cg];
    t1s[n * 65 + cg * 4 + 0] = ssp(a0 + b14.x);
    t1s[n * 65 + cg * 4 + 1] = ssp(a1 + b14.y);
    t1s[n * 65 + cg * 4 + 2] = ssp(a2 + b14.z);
    t1s[n * 65 + cg * 4 + 3] = ssp(a3 + b14.w);
    __syncthreads();
    a0 = a1 = a2 = a3 = 0.f;
    const float4* M2 = (const float4*)m2;   // [64][16 float4]
#pragma unroll 4
    for (int k = 0; k < 64; k++) {
        float xv = t1s[n * 65 + k];
        float4 w = M2[k * 16 + cg];
        a0 = fmaf(xv, w.x, a0);
        a1 = fmaf(xv, w.y, a1);
        a2 = fmaf(xv, w.z, a2);
        a3 = fmaf(xv, w.w, a3);
    }
    float4 b24 = ((const float4*)mb2)[cg];
    float4* xp = (float4*)g_x + (n0 + n) * 16 + cg;
    float4 xv4 = *xp;
    xv4.x += a0 + b24.x;
    xv4.y += a1 + b24.y;
    xv4.z += a2 + b24.z;
    xv4.w += a3 + b24.w;
    *xp = xv4;
}

// ---------------- output head ----------------
__global__ void zero_out(float* out) {
    if (threadIdx.x < BB) out[threadIdx.x] = 0.f;
}

__global__ void out_kernel(const float* __restrict__ w1,
                           const float* __restrict__ b1,
                           const float* __restrict__ w2,
                           const float* __restrict__ b2,
                           const int* __restrict__ gid,
                           float* __restrict__ out) {
    int n = blockIdx.x;
    int t = threadIdx.x;  // 128
    __shared__ float xs[DD];
    __shared__ float red[4];
    if (t < DD) xs[t] = g_x[n * DD + t];
    __syncthreads();
    float acc = b1[t];
#pragma unroll
    for (int k = 0; k < DD; k++) acc = fmaf(xs[k], w1[k * 128 + t], acc);
    float p = ssp(acc) * w2[t];
#pragma unroll
    for (int o = 16; o > 0; o >>= 1) p += __shfl_down_sync(0xffffffffu, p, o);
    if ((t & 31) == 0) red[t >> 5] = p;
    __syncthreads();
    if (t == 0) {
        float hh = red[0] + red[1] + red[2] + red[3] + b2[0];
        atomicAdd(&out[gid[n]], hh);
    }
}

extern "C" void kernel_launch(void* const* d_in, const int* in_sizes, int n_in,
                              void* d_out, int out_size) {
    const float* R    = (const float*)d_in[0];
    const int*   Z    = (const int*)d_in[1];
    const int*   src  = (const int*)d_in[2];
    const int*   dst  = (const int*)d_in[3];
    const int*   gid  = (const int*)d_in[4];
    const float* emb  = (const float*)d_in[5];
    const float* off  = (const float*)d_in[6];
    const float* wid  = (const float*)d_in[7];
    const float* fcw  = (const float*)d_in[8];
    const float* al   = (const float*)d_in[9];
    const float* ar   = (const float*)d_in[10];
    const float* fw1  = (const float*)d_in[11];
    const float* fb1  = (const float*)d_in[12];
    const float* fw2  = (const float*)d_in[13];
    const float* fb2  = (const float*)d_in[14];
    const float* m1   = (const float*)d_in[15];
    const float* mb1  = (const float*)d_in[16];
    const float* m2   = (const float*)d_in[17];
    const float* mb2  = (const float*)d_in[18];
    const float* ow1  = (const float*)d_in[19];
    const float* ob1  = (const float*)d_in[20];
    const float* ow2  = (const float*)d_in[21];
    const float* ob2  = (const float*)d_in[22];
    float* out = (float*)d_out;

    zero_deg<<<(NN + 255) / 256, 256>>>();
    count_deg<<<(EE + 255) / 256, 256>>>(dst);
    scan_kernel<<<1, 1024>>>();
    scatter_kernel<<<(EE + 255) / 256, 256>>>(R, src, dst);
    embed_kernel<<<(NN * DD + 255) / 256, 256>>>(Z, emb);

    for (int l = 0; l < LLAYERS; l++) {
        nodes_pre<<<NN / NB, 256>>>(fcw + l * DD * HD, al + l * HHD * DD, ar + l * HHD * DD);
        build_table<<<TBL + 1, 128>>>(off, wid,
                                      fw1 + l * GG * HD, fb1 + l * HD,
                                      fw2 + l * HIDN * HD, fb2 + l * HD);
        edge_ex<<<(EE + 255) / 256, 256>>>();
        gather_v<<<NN, 128>>>();
        nodes_mlp<<<NN / NB, 256>>>(m1 + l * HD * DD, mb1 + l * DD,
                                    m2 + l * DD * DD, mb2 + l * DD);
    }

    zero_out<<<1, 64>>>(out);
    out_kernel<<<NN, 128>>>(ow1, ob1, ow2, ob2, gid, out);
}

// round 6
// speedup vs baseline: 1.2874x; 1.2494x over previous
#include <cuda_runtime.h>
#include <cuda_fp16.h>
#include <math.h>

#define NN 50000
#define EE 800000
#define BB 64
#define DD 64
#define HHD 2
#define GG 50
#define HIDN 128
#define HD 128
#define LLAYERS 3
#define TBL 2048
#define TBL_SCALE 256.0f     // TBL / 8.0
#define NB 16
#define SCAN_BLKS 49         // ceil(NN/1024)

// ---- scratch ----
__device__ float  g_x[NN * DD];
__device__ uint4  g_hh[NN * 16];        // fp16 h, 16B-aligned (128 halfs/node)
__device__ float  g_v[NN * HD];
__device__ float  g_el[NN * HHD];
__device__ float  g_er[NN * HHD];
__device__ int    g_deg[NN];
__device__ int    g_rowptr[NN + 1];
__device__ int    g_wpos[NN];
__device__ int    g_btot[SCAN_BLKS];
__device__ int    g_boff[SCAN_BLKS];
__device__ float2 g_su[EE];             // {u = r*TBL_SCALE (or TBL), bitcast(src)}
__device__ __half2 g_T2[(TBL + 1) * HD];

__device__ __forceinline__ float ssp(float x) {
    return fmaxf(x, 0.f) + log1pf(expf(-fabsf(x))) - 0.69314718055994531f;
}

// ---------------- CSR build ----------------
__global__ void zero_deg() {
    int i = blockIdx.x * blockDim.x + threadIdx.x;
    if (i < NN) g_deg[i] = 0;
}

__global__ void count_deg(const int* __restrict__ dst) {
    int e = blockIdx.x * blockDim.x + threadIdx.x;
    if (e < EE) atomicAdd(&g_deg[dst[e]], 1);
}

// two-level scan: per-block inclusive + totals
__global__ void scan1() {
    __shared__ int sh[1024];
    int t = threadIdx.x;
    int idx = blockIdx.x * 1024 + t;
    int v = (idx < NN) ? g_deg[idx] : 0;
    sh[t] = v;
    __syncthreads();
#pragma unroll
    for (int o = 1; o < 1024; o <<= 1) {
        int x = (t >= o) ? sh[t - o] : 0;
        __syncthreads();
        sh[t] += x;
        __syncthreads();
    }
    if (idx < NN) g_wpos[idx] = sh[t];           // inclusive (temp)
    if (t == 1023) g_btot[blockIdx.x] = sh[1023];
}

__global__ void scan2() {   // 1 block, 64 threads
    __shared__ int sh[64];
    int t = threadIdx.x;
    int v = (t < SCAN_BLKS) ? g_btot[t] : 0;
    sh[t] = v;
    __syncthreads();
#pragma unroll
    for (int o = 1; o < 64; o <<= 1) {
        int x = (t >= o) ? sh[t - o] : 0;
        __syncthreads();
        sh[t] += x;
        __syncthreads();
    }
    if (t < SCAN_BLKS) g_boff[t] = sh[t] - v;    // exclusive
    if (t == SCAN_BLKS - 1) g_rowptr[NN] = sh[t];
}

__global__ void scan3() {
    int idx = blockIdx.x * blockDim.x + threadIdx.x;
    if (idx >= NN) return;
    int excl = g_boff[idx >> 10] + g_wpos[idx] - g_deg[idx];
    g_rowptr[idx] = excl;
    g_wpos[idx] = excl;
}

__global__ void scatter_kernel(const float* __restrict__ R,
                               const int* __restrict__ src,
                               const int* __restrict__ dst) {
    int e = blockIdx.x * blockDim.x + threadIdx.x;
    if (e >= EE) return;
    int s = src[e], d = dst[e];
    float dx = R[s * 3 + 0] - R[d * 3 + 0];
    float dy = R[s * 3 + 1] - R[d * 3 + 1];
    float dz = R[s * 3 + 2] - R[d * 3 + 2];
    float r = sqrtf(dx * dx + dy * dy + dz * dz);
    int pos = atomicAdd(&g_wpos[d], 1);
    float u = (r < 8.0f) ? r * TBL_SCALE : (float)TBL;  // TBL row zeroed
    g_su[pos] = make_float2(u, __int_as_float(s));
}

// ---------------- embedding gather ----------------
__global__ void embed_kernel(const int* __restrict__ Z,
                             const float* __restrict__ emb) {
    int i = blockIdx.x * blockDim.x + threadIdx.x;
    if (i >= NN * DD) return;
    int n = i >> 6, d = i & 63;
    g_x[i] = emb[Z[n] * DD + d];
}

// ---------------- batched node pre: h(fp16) = x @ fcw, el/er logits ----------------
__global__ void __launch_bounds__(256) nodes_pre(const float* __restrict__ fcw,
                                                 const float* __restrict__ al,
                                                 const float* __restrict__ ar) {
    int n0 = blockIdx.x * NB;
    int t = threadIdx.x;
    __shared__ float xs[NB * 65];
    __shared__ float els[NB * 2], ers[NB * 2];
    for (int i = t; i < NB * 64; i += 256)
        xs[(i >> 6) * 65 + (i & 63)] = g_x[n0 * 64 + i];
    if (t < NB * 2) { els[t] = 0.f; ers[t] = 0.f; }
    __syncthreads();
    int n = t & 15, cg = t >> 4;
    float acc[8];
#pragma unroll
    for (int j = 0; j < 8; j++) acc[j] = 0.f;
    const float4* W4 = (const float4*)fcw;
#pragma unroll 4
    for (int k = 0; k < 64; k++) {
        float xv = xs[n * 65 + k];
        float4 wa = W4[k * 32 + cg * 2];
        float4 wb = W4[k * 32 + cg * 2 + 1];
        acc[0] = fmaf(xv, wa.x, acc[0]);
        acc[1] = fmaf(xv, wa.y, acc[1]);
        acc[2] = fmaf(xv, wa.z, acc[2]);
        acc[3] = fmaf(xv, wa.w, acc[3]);
        acc[4] = fmaf(xv, wb.x, acc[4]);
        acc[5] = fmaf(xv, wb.y, acc[5]);
        acc[6] = fmaf(xv, wb.z, acc[6]);
        acc[7] = fmaf(xv, wb.w, acc[7]);
    }
    int ng = n0 + n;
    __half2 hp[4];
    hp[0] = __floats2half2_rn(acc[0], acc[1]);
    hp[1] = __floats2half2_rn(acc[2], acc[3]);
    hp[2] = __floats2half2_rn(acc[4], acc[5]);
    hp[3] = __floats2half2_rn(acc[6], acc[7]);
    g_hh[ng * 16 + cg] = *reinterpret_cast<uint4*>(hp);
    int head = cg >> 3;
    int ca = (cg * 8) & 63;
    float4 ala = ((const float4*)al)[head * 16 + (ca >> 2)];
    float4 alb = ((const float4*)al)[head * 16 + (ca >> 2) + 1];
    float4 ara = ((const float4*)ar)[head * 16 + (ca >> 2)];
    float4 arb = ((const float4*)ar)[head * 16 + (ca >> 2) + 1];
    float pl = acc[0]*ala.x + acc[1]*ala.y + acc[2]*ala.z + acc[3]*ala.w
             + acc[4]*alb.x + acc[5]*alb.y + acc[6]*alb.z + acc[7]*alb.w;
    float pr = acc[0]*ara.x + acc[1]*ara.y + acc[2]*ara.z + acc[3]*ara.w
             + acc[4]*arb.x + acc[5]*arb.y + acc[6]*arb.z + acc[7]*arb.w;
    atomicAdd(&els[n * 2 + head], pl);
    atomicAdd(&ers[n * 2 + head], pr);
    __syncthreads();
    if (t < NB * 2) {
        g_el[n0 * 2 + t] = els[t];
        g_er[n0 * 2 + t] = ers[t];
    }
}

// ---------------- build fp16 pair-packed table ----------------
__global__ void build_table(const float* __restrict__ off,
                            const float* __restrict__ wid,
                            const float* __restrict__ w1,
                            const float* __restrict__ b1,
                            const float* __restrict__ w2,
                            const float* __restrict__ b2) {
    int i = blockIdx.x;       // 0..TBL
    int t = threadIdx.x;      // 128
    __shared__ float gs[2][GG];
    __shared__ float hid[2][HIDN];
    float v01[2];
#pragma unroll
    for (int q = 0; q < 2; q++) {
        float r = (float)(i + q) * (8.0f / (float)TBL);
        if (t < GG) {
            float w = wid[t];
            float coef = -0.5f / (w * w);
            float dr = r - off[t];
            gs[q][t] = expf(coef * dr * dr);
        }
    }
    __syncthreads();
#pragma unroll
    for (int q = 0; q < 2; q++) {
        float acc = b1[t];
#pragma unroll
        for (int g = 0; g < GG; g++) acc = fmaf(gs[q][g], w1[g * HD + t], acc);
        hid[q][t] = ssp(acc);
    }
    __syncthreads();
#pragma unroll
    for (int q = 0; q < 2; q++) {
        float acc2 = b2[t];
#pragma unroll 8
        for (int k = 0; k < HIDN; k++) acc2 = fmaf(hid[q][k], w2[k * HD + t], acc2);
        float r = (float)(i + q) * (8.0f / (float)TBL);
        float C = (r < 8.0f) ? 0.5f * (cosf(r * 0.39269908169872414f) + 1.0f) : 0.0f;
        v01[q] = acc2 * C;
    }
    if (i == TBL) { v01[0] = 0.f; v01[1] = 0.f; }   // skip row
    g_T2[i * HD + t] = __floats2half2_rn(v01[0], v01[1]);
}

// ---------------- gather (fused attention): v = ssp(softmax-weighted msg sum) ----------------
__global__ void __launch_bounds__(128) gather_v() {
    int n = blockIdx.x;
    int t = threadIdx.x;
    int beg = g_rowptr[n];
    int end = g_rowptr[n + 1];
    float2 er = ((const float2*)g_er)[n];
    __shared__ float sh_u[32];
    __shared__ int   sh_s[32];
    __shared__ float sh_e0[32], sh_e1[32];
    float acc = 0.f, exs = 0.f;
    const __half* hh = (const __half*)g_hh;
    for (int base = beg; base < end; base += 32) {
        int cnt = min(32, end - base);
        __syncthreads();
        if (t < cnt) {
            float2 su = g_su[base + t];
            int s = __float_as_int(su.y);
            float2 el = ((const float2*)g_el)[s];
            float ev0 = el.x + er.x; ev0 = ev0 > 0.f ? ev0 : 0.2f * ev0;
            float ev1 = el.y + er.y; ev1 = ev1 > 0.f ? ev1 : 0.2f * ev1;
            sh_u[t] = su.x; sh_s[t] = s;
            sh_e0[t] = expf(ev0); sh_e1[t] = expf(ev1);
        }
        __syncthreads();
#pragma unroll 4
        for (int c = 0; c < cnt; c++) {
            float u = sh_u[c];
            int s = sh_s[c];
            int i = (int)u;
            float f = u - (float)i;
            float2 tf = __half22float2(g_T2[i * HD + t]);
            float w = fmaf(f, tf.y - tf.x, tf.x);
            float h = __half2float(hh[s * HD + t]);
            float exh = (t < 64) ? sh_e0[c] : sh_e1[c];
            acc = fmaf(h * w, exh, acc);
            exs += exh;
        }
    }
    float a = (exs > 0.f) ? acc / exs : 0.f;
    g_v[n * HD + t] = ssp(a);
}

// ---------------- batched node MLP: x += m2(ssp(m1(v))) ----------------
__global__ void __launch_bounds__(256) nodes_mlp(const float* __restrict__ m1,
                                                 const float* __restrict__ mb1,
                                                 const float* __restrict__ m2,
                                                 const float* __restrict__ mb2) {
    int n0 = blockIdx.x * NB;
    int t = threadIdx.x;
    __shared__ float vs[NB * 129];
    __shared__ float t1s[NB * 65];
    for (int i = t; i < NB * 128; i += 256)
        vs[(i >> 7) * 129 + (i & 127)] = g_v[n0 * 128 + i];
    __syncthreads();
    int n = t & 15, cg = t >> 4;
    float a0 = 0.f, a1 = 0.f, a2 = 0.f, a3 = 0.f;
    const float4* M1 = (const float4*)m1;
#pragma unroll 4
    for (int k = 0; k < 128; k++) {
        float xv = vs[n * 129 + k];
        float4 w = M1[k * 16 + cg];
        a0 = fmaf(xv, w.x, a0);
        a1 = fmaf(xv, w.y, a1);
        a2 = fmaf(xv, w.z, a2);
        a3 = fmaf(xv, w.w, a3);
    }
    float4 b14 = ((const float4*)mb1)[cg];
    t1s[n * 65 + cg * 4 + 0] = ssp(a0 + b14.x);
    t1s[n * 65 + cg * 4 + 1] = ssp(a1 + b14.y);
    t1s[n * 65 + cg * 4 + 2] = ssp(a2 + b14.z);
    t1s[n * 65 + cg * 4 + 3] = ssp(a3 + b14.w);
    __syncthreads();
    a0 = a1 = a2 = a3 = 0.f;
    const float4* M2 = (const float4*)m2;
#pragma unroll 4
    for (int k = 0; k < 64; k++) {
        float xv = t1s[n * 65 + k];
        float4 w = M2[k * 16 + cg];
        a0 = fmaf(xv, w.x, a0);
        a1 = fmaf(xv, w.y, a1);
        a2 = fmaf(xv, w.z, a2);
        a3 = fmaf(xv, w.w, a3);
    }
    float4 b24 = ((const float4*)mb2)[cg];
    float4* xp = (float4*)g_x + (n0 + n) * 16 + cg;
    float4 xv4 = *xp;
    xv4.x += a0 + b24.x;
    xv4.y += a1 + b24.y;
    xv4.z += a2 + b24.z;
    xv4.w += a3 + b24.w;
    *xp = xv4;
}

// ---------------- output head (batched 16 nodes/block) ----------------
__global__ void zero_out(float* out) {
    if (threadIdx.x < BB) out[threadIdx.x] = 0.f;
}

__global__ void __launch_bounds__(256) out_batch(const float* __restrict__ w1,
                                                 const float* __restrict__ b1,
                                                 const float* __restrict__ w2,
                                                 const float* __restrict__ b2,
                                                 const int* __restrict__ gid,
                                                 float* __restrict__ out) {
    int n0 = blockIdx.x * NB;
    int t = threadIdx.x;
    __shared__ float xs[NB * 65];
    __shared__ float sred[16][17];
    for (int i = t; i < NB * 64; i += 256)
        xs[(i >> 6) * 65 + (i & 63)] = g_x[n0 * 64 + i];
    __syncthreads();
    int n = t & 15, cg = t >> 4;
    float acc[8];
#pragma unroll
    for (int j = 0; j < 8; j++) acc[j] = 0.f;
    const float4* W4 = (const float4*)w1;   // [64][32 float4]
#pragma unroll 4
    for (int k = 0; k < 64; k++) {
        float xv = xs[n * 65 + k];
        float4 wa = W4[k * 32 + cg * 2];
        float4 wb = W4[k * 32 + cg * 2 + 1];
        acc[0] = fmaf(xv, wa.x, acc[0]);
        acc[1] = fmaf(xv, wa.y, acc[1]);
        acc[2] = fmaf(xv, wa.z, acc[2]);
        acc[3] = fmaf(xv, wa.w, acc[3]);
        acc[4] = fmaf(xv, wb.x, acc[4]);
        acc[5] = fmaf(xv, wb.y, acc[5]);
        acc[6] = fmaf(xv, wb.z, acc[6]);
        acc[7] = fmaf(xv, wb.w, acc[7]);
    }
    float4 b1a = ((const float4*)b1)[cg * 2];
    float4 b1b = ((const float4*)b1)[cg * 2 + 1];
    float4 w2a = ((const float4*)w2)[cg * 2];
    float4 w2b = ((const float4*)w2)[cg * 2 + 1];
    float p = ssp(acc[0] + b1a.x) * w2a.x + ssp(acc[1] + b1a.y) * w2a.y
            + ssp(acc[2] + b1a.z) * w2a.z + ssp(acc[3] + b1a.w) * w2a.w
            + ssp(acc[4] + b1b.x) * w2b.x + ssp(acc[5] + b1b.y) * w2b.y
            + ssp(acc[6] + b1b.z) * w2b.z + ssp(acc[7] + b1b.w) * w2b.w;
    sred[cg][n] = p;
    __syncthreads();
    if (t < 16) {
        float s = b2[0];
#pragma unroll
        for (int c = 0; c < 16; c++) s += sred[c][t];
        atomicAdd(&out[gid[n0 + t]], s);
    }
}

extern "C" void kernel_launch(void* const* d_in, const int* in_sizes, int n_in,
                              void* d_out, int out_size) {
    const float* R    = (const float*)d_in[0];
    const int*   Z    = (const int*)d_in[1];
    const int*   src  = (const int*)d_in[2];
    const int*   dst  = (const int*)d_in[3];
    const int*   gid  = (const int*)d_in[4];
    const float* emb  = (const float*)d_in[5];
    const float* off  = (const float*)d_in[6];
    const float* wid  = (const float*)d_in[7];
    const float* fcw  = (const float*)d_in[8];
    const float* al   = (const float*)d_in[9];
    const float* ar   = (const float*)d_in[10];
    const float* fw1  = (const float*)d_in[11];
    const float* fb1  = (const float*)d_in[12];
    const float* fw2  = (const float*)d_in[13];
    const float* fb2  = (const float*)d_in[14];
    const float* m1   = (const float*)d_in[15];
    const float* mb1  = (const float*)d_in[16];
    const float* m2   = (const float*)d_in[17];
    const float* mb2  = (const float*)d_in[18];
    const float* ow1  = (const float*)d_in[19];
    const float* ob1  = (const float*)d_in[20];
    const float* ow2  = (const float*)d_in[21];
    const float* ob2  = (const float*)d_in[22];
    float* out = (float*)d_out;

    zero_deg<<<(NN + 255) / 256, 256>>>();
    count_deg<<<(EE + 255) / 256, 256>>>(dst);
    scan1<<<SCAN_BLKS, 1024>>>();
    scan2<<<1, 64>>>();
    scan3<<<(NN + 255) / 256, 256>>>();
    scatter_kernel<<<(EE + 255) / 256, 256>>>(R, src, dst);
    embed_kernel<<<(NN * DD + 255) / 256, 256>>>(Z, emb);

    for (int l = 0; l < LLAYERS; l++) {
        nodes_pre<<<NN / NB, 256>>>(fcw + l * DD * HD, al + l * HHD * DD, ar + l * HHD * DD);
        build_table<<<TBL + 1, 128>>>(off, wid,
                                      fw1 + l * GG * HD, fb1 + l * HD,
                                      fw2 + l * HIDN * HD, fb2 + l * HD);
        gather_v<<<NN, 128>>>();
        nodes_mlp<<<NN / NB, 256>>>(m1 + l * HD * DD, mb1 + l * DD,
                                    m2 + l * DD * DD, mb2 + l * DD);
    }

    zero_out<<<1, 64>>>(out);
    out_batch<<<NN / NB, 256>>>(ow1, ob1, ow2, ob2, gid, out);
}

// round 7
// speedup vs baseline: 1.7985x; 1.3970x over previous
#include <cuda_runtime.h>
#include <cuda_fp16.h>
#include <math.h>

#define NN 50000
#define EE 800000
#define BB 64
#define DD 64
#define HHD 2
#define GG 50
#define HIDN 128
#define HD 128
#define LLAYERS 3
#define TBL 4096
#define TBL_SCALE 512.0f     // TBL / 8.0
#define NB 32                // nodes per block in node GEMM kernels
#define SCAN_BLKS 49         // ceil(NN/1024)

// ---- scratch ----
__device__ float  g_x[NN * DD];
__device__ uint4  g_hh[NN * 16];        // fp16 h (128 halfs/node)
__device__ float  g_v[NN * HD];
__device__ float  g_el[NN * HHD];
__device__ float  g_er[NN * HHD];
__device__ int    g_deg[NN];
__device__ int    g_rowptr[NN + 1];
__device__ int    g_wpos[NN];
__device__ int    g_btot[SCAN_BLKS];
__device__ int    g_boff[SCAN_BLKS];
__device__ float2 g_su[EE];             // {u = r*TBL_SCALE (or TBL), bitcast(src)}
__device__ __half g_Tn[(TBL + 1) * HD]; // nearest-neighbor w(r)*C(r) table, 1 MB

__device__ __forceinline__ float ssp(float x) {
    return fmaxf(x, 0.f) + log1pf(expf(-fabsf(x))) - 0.69314718055994531f;
}

// ---------------- CSR build ----------------
__global__ void zero_deg() {
    int i = blockIdx.x * blockDim.x + threadIdx.x;
    if (i < NN) g_deg[i] = 0;
}

__global__ void count_deg(const int* __restrict__ dst) {
    int e = blockIdx.x * blockDim.x + threadIdx.x;
    if (e < EE) atomicAdd(&g_deg[dst[e]], 1);
}

__global__ void scan1() {
    __shared__ int sh[1024];
    int t = threadIdx.x;
    int idx = blockIdx.x * 1024 + t;
    int v = (idx < NN) ? g_deg[idx] : 0;
    sh[t] = v;
    __syncthreads();
#pragma unroll
    for (int o = 1; o < 1024; o <<= 1) {
        int x = (t >= o) ? sh[t - o] : 0;
        __syncthreads();
        sh[t] += x;
        __syncthreads();
    }
    if (idx < NN) g_wpos[idx] = sh[t];
    if (t == 1023) g_btot[blockIdx.x] = sh[1023];
}

__global__ void scan2() {
    __shared__ int sh[64];
    int t = threadIdx.x;
    int v = (t < SCAN_BLKS) ? g_btot[t] : 0;
    sh[t] = v;
    __syncthreads();
#pragma unroll
    for (int o = 1; o < 64; o <<= 1) {
        int x = (t >= o) ? sh[t - o] : 0;
        __syncthreads();
        sh[t] += x;
        __syncthreads();
    }
    if (t < SCAN_BLKS) g_boff[t] = sh[t] - v;
    if (t == SCAN_BLKS - 1) g_rowptr[NN] = sh[t];
}

__global__ void scan3() {
    int idx = blockIdx.x * blockDim.x + threadIdx.x;
    if (idx >= NN) return;
    int excl = g_boff[idx >> 10] + g_wpos[idx] - g_deg[idx];
    g_rowptr[idx] = excl;
    g_wpos[idx] = excl;
}

__global__ void scatter_kernel(const float* __restrict__ R,
                               const int* __restrict__ src,
                               const int* __restrict__ dst) {
    int e = blockIdx.x * blockDim.x + threadIdx.x;
    if (e >= EE) return;
    int s = src[e], d = dst[e];
    float dx = R[s * 3 + 0] - R[d * 3 + 0];
    float dy = R[s * 3 + 1] - R[d * 3 + 1];
    float dz = R[s * 3 + 2] - R[d * 3 + 2];
    float r = sqrtf(dx * dx + dy * dy + dz * dz);
    int pos = atomicAdd(&g_wpos[d], 1);
    float u = (r < 8.0f) ? r * TBL_SCALE : (float)TBL;   // row TBL is zeroed
    g_su[pos] = make_float2(u, __int_as_float(s));
}

// ---------------- embedding gather ----------------
__global__ void embed_kernel(const int* __restrict__ Z,
                             const float* __restrict__ emb) {
    int i = blockIdx.x * blockDim.x + threadIdx.x;
    if (i >= NN * DD) return;
    int n = i >> 6, d = i & 63;
    g_x[i] = emb[Z[n] * DD + d];
}

// ---------------- batched node pre: h(fp16) = x @ fcw, el/er logits ----------------
// 32 nodes/block, 256 threads; thread handles nodes (t&15) and (t&15)+16, cols cg*8..cg*8+7
__global__ void __launch_bounds__(256) nodes_pre(const float* __restrict__ fcw,
                                                 const float* __restrict__ al,
                                                 const float* __restrict__ ar) {
    int n0 = blockIdx.x * NB;
    int t = threadIdx.x;
    __shared__ float xs[NB * 65];
    __shared__ float els[NB * 2], ers[NB * 2];
    for (int i = t; i < NB * 64; i += 256)
        xs[(i >> 6) * 65 + (i & 63)] = g_x[n0 * 64 + i];
    if (t < NB * 2) { els[t] = 0.f; ers[t] = 0.f; }
    __syncthreads();
    int nA = t & 15, nB = nA + 16, cg = t >> 4;
    float aA[8], aB[8];
#pragma unroll
    for (int j = 0; j < 8; j++) { aA[j] = 0.f; aB[j] = 0.f; }
    const float4* W4 = (const float4*)fcw;
#pragma unroll 4
    for (int k = 0; k < 64; k++) {
        float xA = xs[nA * 65 + k];
        float xB = xs[nB * 65 + k];
        float4 wa = W4[k * 32 + cg * 2];
        float4 wb = W4[k * 32 + cg * 2 + 1];
        aA[0] = fmaf(xA, wa.x, aA[0]); aB[0] = fmaf(xB, wa.x, aB[0]);
        aA[1] = fmaf(xA, wa.y, aA[1]); aB[1] = fmaf(xB, wa.y, aB[1]);
        aA[2] = fmaf(xA, wa.z, aA[2]); aB[2] = fmaf(xB, wa.z, aB[2]);
        aA[3] = fmaf(xA, wa.w, aA[3]); aB[3] = fmaf(xB, wa.w, aB[3]);
        aA[4] = fmaf(xA, wb.x, aA[4]); aB[4] = fmaf(xB, wb.x, aB[4]);
        aA[5] = fmaf(xA, wb.y, aA[5]); aB[5] = fmaf(xB, wb.y, aB[5]);
        aA[6] = fmaf(xA, wb.z, aA[6]); aB[6] = fmaf(xB, wb.z, aB[6]);
        aA[7] = fmaf(xA, wb.w, aA[7]); aB[7] = fmaf(xB, wb.w, aB[7]);
    }
    __half2 hp[4];
    hp[0] = __floats2half2_rn(aA[0], aA[1]);
    hp[1] = __floats2half2_rn(aA[2], aA[3]);
    hp[2] = __floats2half2_rn(aA[4], aA[5]);
    hp[3] = __floats2half2_rn(aA[6], aA[7]);
    g_hh[(n0 + nA) * 16 + cg] = *reinterpret_cast<uint4*>(hp);
    hp[0] = __floats2half2_rn(aB[0], aB[1]);
    hp[1] = __floats2half2_rn(aB[2], aB[3]);
    hp[2] = __floats2half2_rn(aB[4], aB[5]);
    hp[3] = __floats2half2_rn(aB[6], aB[7]);
    g_hh[(n0 + nB) * 16 + cg] = *reinterpret_cast<uint4*>(hp);

    int head = cg >> 3;
    int ca = (cg * 8) & 63;
    float4 ala = ((const float4*)al)[head * 16 + (ca >> 2)];
    float4 alb = ((const float4*)al)[head * 16 + (ca >> 2) + 1];
    float4 ara = ((const float4*)ar)[head * 16 + (ca >> 2)];
    float4 arb = ((const float4*)ar)[head * 16 + (ca >> 2) + 1];
    float plA = aA[0]*ala.x + aA[1]*ala.y + aA[2]*ala.z + aA[3]*ala.w
              + aA[4]*alb.x + aA[5]*alb.y + aA[6]*alb.z + aA[7]*alb.w;
    float prA = aA[0]*ara.x + aA[1]*ara.y + aA[2]*ara.z + aA[3]*ara.w
              + aA[4]*arb.x + aA[5]*arb.y + aA[6]*arb.z + aA[7]*arb.w;
    float plB = aB[0]*ala.x + aB[1]*ala.y + aB[2]*ala.z + aB[3]*ala.w
              + aB[4]*alb.x + aB[5]*alb.y + aB[6]*alb.z + aB[7]*alb.w;
    float prB = aB[0]*ara.x + aB[1]*ara.y + aB[2]*ara.z + aB[3]*ara.w
              + aB[4]*arb.x + aB[5]*arb.y + aB[6]*arb.z + aB[7]*arb.w;
    atomicAdd(&els[nA * 2 + head], plA);
    atomicAdd(&ers[nA * 2 + head], prA);
    atomicAdd(&els[nB * 2 + head], plB);
    atomicAdd(&ers[nB * 2 + head], prB);
    __syncthreads();
    if (t < NB * 2) {
        g_el[n0 * 2 + t] = els[t];
        g_er[n0 * 2 + t] = ers[t];
    }
}

// ---------------- build nearest-neighbor fp16 table ----------------
__global__ void build_table(const float* __restrict__ off,
                            const float* __restrict__ wid,
                            const float* __restrict__ w1,
                            const float* __restrict__ b1,
                            const float* __restrict__ w2,
                            const float* __restrict__ b2) {
    int i = blockIdx.x;       // 0..TBL
    int t = threadIdx.x;      // 128
    __shared__ float gs[GG];
    __shared__ float hid[HIDN];
    float r = (float)i * (8.0f / (float)TBL);
    if (t < GG) {
        float w = wid[t];
        float coef = -0.5f / (w * w);
        float dr = r - off[t];
        gs[t] = expf(coef * dr * dr);
    }
    __syncthreads();
    float acc = b1[t];
#pragma unroll
    for (int g = 0; g < GG; g++) acc = fmaf(gs[g], w1[g * HD + t], acc);
    hid[t] = ssp(acc);
    __syncthreads();
    float acc2 = b2[t];
#pragma unroll 8
    for (int k = 0; k < HIDN; k++) acc2 = fmaf(hid[k], w2[k * HD + t], acc2);
    float C = (r < 8.0f) ? 0.5f * (cosf(r * 0.39269908169872414f) + 1.0f) : 0.0f;
    float v = acc2 * C;
    if (i == TBL) v = 0.f;    // skip row (r >= 8)
    g_Tn[i * HD + t] = __float2half(v);
}

// ---------------- gather: warp per node, shfl staging, half2 math ----------------
__global__ void __launch_bounds__(256) gather_v() {
    int wid = threadIdx.x >> 5, lane = threadIdx.x & 31;
    int n = blockIdx.x * 8 + wid;
    if (n >= NN) return;
    int beg = g_rowptr[n], end = g_rowptr[n + 1];
    float2 er = ((const float2*)g_er)[n];
    float a0 = 0.f, a1 = 0.f, a2 = 0.f, a3 = 0.f, exs = 0.f;
    const __half* hh = (const __half*)g_hh;
    for (int base = beg; base < end; base += 32) {
        int cnt = min(32, end - base);
        float u = 0.f, e0 = 0.f, e1 = 0.f;
        int s = 0;
        if (lane < cnt) {
            float2 su = g_su[base + lane];
            u = su.x;
            s = __float_as_int(su.y);
            float2 el = ((const float2*)g_el)[s];
            float ev0 = el.x + er.x; ev0 = ev0 > 0.f ? ev0 : 0.2f * ev0;
            float ev1 = el.y + er.y; ev1 = ev1 > 0.f ? ev1 : 0.2f * ev1;
            e0 = expf(ev0);
            e1 = expf(ev1);
        }
        for (int c = 0; c < cnt; c++) {
            float uc = __shfl_sync(0xffffffffu, u, c);
            int   sc = __shfl_sync(0xffffffffu, s, c);
            float ec0 = __shfl_sync(0xffffffffu, e0, c);
            float ec1 = __shfl_sync(0xffffffffu, e1, c);
            int i = (int)(uc + 0.5f);                      // nearest row
            uint2 tw = *((const uint2*)(g_Tn + i * HD) + lane);
            uint2 hw = *((const uint2*)(hh + sc * HD) + lane);
            __half2 p0 = __hmul2(*(__half2*)&tw.x, *(__half2*)&hw.x);
            __half2 p1 = __hmul2(*(__half2*)&tw.y, *(__half2*)&hw.y);
            float2 f0 = __half22float2(p0);
            float2 f1 = __half22float2(p1);
            float exh = (lane < 16) ? ec0 : ec1;           // feature = lane*4
            a0 = fmaf(f0.x, exh, a0);
            a1 = fmaf(f0.y, exh, a1);
            a2 = fmaf(f1.x, exh, a2);
            a3 = fmaf(f1.y, exh, a3);
            exs += exh;
        }
    }
    float inv = (exs > 0.f) ? 1.0f / exs : 0.f;
    float4 o;
    o.x = ssp(a0 * inv);
    o.y = ssp(a1 * inv);
    o.z = ssp(a2 * inv);
    o.w = ssp(a3 * inv);
    ((float4*)g_v)[n * 32 + lane] = o;
}

// ---------------- batched node MLP: x += m2(ssp(m1(v))) ----------------
// 32 nodes/block, 256 threads; thread handles nodes (t&15),(t&15)+16, cols cg*4..cg*4+3
__global__ void __launch_bounds__(256) nodes_mlp(const float* __restrict__ m1,
                                                 const float* __restrict__ mb1,
                                                 const float* __restrict__ m2,
                                                 const float* __restrict__ mb2) {
    int n0 = blockIdx.x * NB;
    int t = threadIdx.x;
    __shared__ float vs[NB * 129];
    __shared__ float t1s[NB * 65];
    for (int i = t; i < NB * 128; i += 256)
        vs[(i >> 7) * 129 + (i & 127)] = g_v[n0 * 128 + i];
    __syncthreads();
    int nA = t & 15, nB = nA + 16, cg = t >> 4;
    float aA0 = 0.f, aA1 = 0.f, aA2 = 0.f, aA3 = 0.f;
    float aB0 = 0.f, aB1 = 0.f, aB2 = 0.f, aB3 = 0.f;
    const float4* M1 = (const float4*)m1;
#pragma unroll 4
    for (int k = 0; k < 128; k++) {
        float xA = vs[nA * 129 + k];
        float xB = vs[nB * 129 + k];
        float4 w = M1[k * 16 + cg];
        aA0 = fmaf(xA, w.x, aA0); aB0 = fmaf(xB, w.x, aB0);
        aA1 = fmaf(xA, w.y, aA1); aB1 = fmaf(xB, w.y, aB1);
        aA2 = fmaf(xA, w.z, aA2); aB2 = fmaf(xB, w.z, aB2);
        aA3 = fmaf(xA, w.w, aA3); aB3 = fmaf(xB, w.w, aB3);
    }
    float4 b14 = ((const float4*)mb1)[cg];
    t1s[nA * 65 + cg * 4 + 0] = ssp(aA0 + b14.x);
    t1s[nA * 65 + cg * 4 + 1] = ssp(aA1 + b14.y);
    t1s[nA * 65 + cg * 4 + 2] = ssp(aA2 + b14.z);
    t1s[nA * 65 + cg * 4 + 3] = ssp(aA3 + b14.w);
    t1s[nB * 65 + cg * 4 + 0] = ssp(aB0 + b14.x);
    t1s[nB * 65 + cg * 4 + 1] = ssp(aB1 + b14.y);
    t1s[nB * 65 + cg * 4 + 2] = ssp(aB2 + b14.z);
    t1s[nB * 65 + cg * 4 + 3] = ssp(aB3 + b14.w);
    __syncthreads();
    aA0 = aA1 = aA2 = aA3 = 0.f;
    aB0 = aB1 = aB2 = aB3 = 0.f;
    const float4* M2 = (const float4*)m2;
#pragma unroll 4
    for (int k = 0; k < 64; k++) {
        float xA = t1s[nA * 65 + k];
        float xB = t1s[nB * 65 + k];
        float4 w = M2[k * 16 + cg];
        aA0 = fmaf(xA, w.x, aA0); aB0 = fmaf(xB, w.x, aB0);
        aA1 = fmaf(xA, w.y, aA1); aB1 = fmaf(xB, w.y, aB1);
        aA2 = fmaf(xA, w.z, aA2); aB2 = fmaf(xB, w.z, aB2);
        aA3 = fmaf(xA, w.w, aA3); aB3 = fmaf(xB, w.w, aB3);
    }
    float4 b24 = ((const float4*)mb2)[cg];
    float4* xpA = (float4*)g_x + (n0 + nA) * 16 + cg;
    float4 xA4 = *xpA;
    xA4.x += aA0 + b24.x; xA4.y += aA1 + b24.y;
    xA4.z += aA2 + b24.z; xA4.w += aA3 + b24.w;
    *xpA = xA4;
    float4* xpB = (float4*)g_x + (n0 + nB) * 16 + cg;
    float4 xB4 = *xpB;
    xB4.x += aB0 + b24.x; xB4.y += aB1 + b24.y;
    xB4.z += aB2 + b24.z; xB4.w += aB3 + b24.w;
    *xpB = xB4;
}

// ---------------- output head ----------------
__global__ void zero_out(float* out) {
    if (threadIdx.x < BB) out[threadIdx.x] = 0.f;
}

__global__ void __launch_bounds__(256) out_batch(const float* __restrict__ w1,
                                                 const float* __restrict__ b1,
                                                 const float* __restrict__ w2,
                                                 const float* __restrict__ b2,
                                                 const int* __restrict__ gid,
                                                 float* __restrict__ out) {
    int n0 = blockIdx.x * 16;
    int t = threadIdx.x;
    __shared__ float xs[16 * 65];
    __shared__ float sred[16][17];
    for (int i = t; i < 16 * 64; i += 256)
        xs[(i >> 6) * 65 + (i & 63)] = g_x[n0 * 64 + i];
    __syncthreads();
    int n = t & 15, cg = t >> 4;
    float acc[8];
#pragma unroll
    for (int j = 0; j < 8; j++) acc[j] = 0.f;
    const float4* W4 = (const float4*)w1;
#pragma unroll 4
    for (int k = 0; k < 64; k++) {
        float xv = xs[n * 65 + k];
        float4 wa = W4[k * 32 + cg * 2];
        float4 wb = W4[k * 32 + cg * 2 + 1];
        acc[0] = fmaf(xv, wa.x, acc[0]);
        acc[1] = fmaf(xv, wa.y, acc[1]);
        acc[2] = fmaf(xv, wa.z, acc[2]);
        acc[3] = fmaf(xv, wa.w, acc[3]);
        acc[4] = fmaf(xv, wb.x, acc[4]);
        acc[5] = fmaf(xv, wb.y, acc[5]);
        acc[6] = fmaf(xv, wb.z, acc[6]);
        acc[7] = fmaf(xv, wb.w, acc[7]);
    }
    float4 b1a = ((const float4*)b1)[cg * 2];
    float4 b1b = ((const float4*)b1)[cg * 2 + 1];
    float4 w2a = ((const float4*)w2)[cg * 2];
    float4 w2b = ((const float4*)w2)[cg * 2 + 1];
    float p = ssp(acc[0] + b1a.x) * w2a.x + ssp(acc[1] + b1a.y) * w2a.y
            + ssp(acc[2] + b1a.z) * w2a.z + ssp(acc[3] + b1a.w) * w2a.w
            + ssp(acc[4] + b1b.x) * w2b.x + ssp(acc[5] + b1b.y) * w2b.y
            + ssp(acc[6] + b1b.z) * w2b.z + ssp(acc[7] + b1b.w) * w2b.w;
    sred[cg][n] = p;
    __syncthreads();
    if (t < 16) {
        float s = b2[0];
#pragma unroll
        for (int c = 0; c < 16; c++) s += sred[c][t];
        atomicAdd(&out[gid[n0 + t]], s);
    }
}

extern "C" void kernel_launch(void* const* d_in, const int* in_sizes, int n_in,
                              void* d_out, int out_size) {
    const float* R    = (const float*)d_in[0];
    const int*   Z    = (const int*)d_in[1];
    const int*   src  = (const int*)d_in[2];
    const int*   dst  = (const int*)d_in[3];
    const int*   gid  = (const int*)d_in[4];
    const float* emb  = (const float*)d_in[5];
    const float* off  = (const float*)d_in[6];
    const float* wid  = (const float*)d_in[7];
    const float* fcw  = (const float*)d_in[8];
    const float* al   = (const float*)d_in[9];
    const float* ar   = (const float*)d_in[10];
    const float* fw1  = (const float*)d_in[11];
    const float* fb1  = (const float*)d_in[12];
    const float* fw2  = (const float*)d_in[13];
    const float* fb2  = (const float*)d_in[14];
    const float* m1   = (const float*)d_in[15];
    const float* mb1  = (const float*)d_in[16];
    const float* m2   = (const float*)d_in[17];
    const float* mb2  = (const float*)d_in[18];
    const float* ow1  = (const float*)d_in[19];
    const float* ob1  = (const float*)d_in[20];
    const float* ow2  = (const float*)d_in[21];
    const float* ob2  = (const float*)d_in[22];
    float* out = (float*)d_out;

    zero_deg<<<(NN + 255) / 256, 256>>>();
    count_deg<<<(EE + 255) / 256, 256>>>(dst);
    scan1<<<SCAN_BLKS, 1024>>>();
    scan2<<<1, 64>>>();
    scan3<<<(NN + 255) / 256, 256>>>();
    scatter_kernel<<<(EE + 255) / 256, 256>>>(R, src, dst);
    embed_kernel<<<(NN * DD + 255) / 256, 256>>>(Z, emb);

    for (int l = 0; l < LLAYERS; l++) {
        nodes_pre<<<NN / NB + 1, 256>>>(fcw + l * DD * HD, al + l * HHD * DD, ar + l * HHD * DD);
        build_table<<<TBL + 1, 128>>>(off, wid,
                                      fw1 + l * GG * HD, fb1 + l * HD,
                                      fw2 + l * HIDN * HD, fb2 + l * HD);
        gather_v<<<(NN + 7) / 8, 256>>>();
        nodes_mlp<<<NN / NB + 1, 256>>>(m1 + l * HD * DD, mb1 + l * DD,
                                        m2 + l * DD * DD, mb2 + l * DD);
    }

    zero_out<<<1, 64>>>(out);
    out_batch<<<NN / 16 + 1, 256>>>(ow1, ob1, ow2, ob2, gid, out);
}

// round 9
// speedup vs baseline: 1.9171x; 1.0659x over previous
#include <cuda_runtime.h>
#include <cuda_fp16.h>
#include <math.h>

#define NN 50000
#define EE 800000
#define BB 64
#define DD 64
#define GG 50
#define HIDN 128
#define HD 128
#define LLAYERS 3
#define TBL 4096
#define TBL_SCALE 512.0f
#define SCAN_BLKS 49
#define TROWS 4
#define TBLK 1025            // ceil((TBL+1)/TROWS)

// ---- scratch ----
__device__ float  g_x[NN * DD];
__device__ uint4  g_hh[NN * 16];
__device__ float  g_v[NN * HD];
__device__ __align__(8) float g_el[NN * 2];
__device__ __align__(8) float g_er[NN * 2];
__device__ int    g_deg[NN];
__device__ int    g_rowptr[NN + 1];
__device__ int    g_wpos[NN];
__device__ int    g_btot[SCAN_BLKS];
__device__ int    g_boff[SCAN_BLKS];
__device__ float2 g_su[EE];
__device__ __half g_Tn[LLAYERS * (TBL + 1) * HD];   // 3.1 MB

__device__ __forceinline__ float ssp(float x) {
    return fmaxf(x, 0.f) + log1pf(expf(-fabsf(x))) - 0.69314718055994531f;
}

// ---------------- CSR build ----------------
__global__ void zero_deg() {
    int i = blockIdx.x * blockDim.x + threadIdx.x;
    if (i < NN) g_deg[i] = 0;
}
__global__ void count_deg(const int* __restrict__ dst) {
    int e = blockIdx.x * blockDim.x + threadIdx.x;
    if (e < EE) atomicAdd(&g_deg[dst[e]], 1);
}
__global__ void scan1() {
    __shared__ int sh[1024];
    int t = threadIdx.x;
    int idx = blockIdx.x * 1024 + t;
    int v = (idx < NN) ? g_deg[idx] : 0;
    sh[t] = v;
    __syncthreads();
#pragma unroll
    for (int o = 1; o < 1024; o <<= 1) {
        int x = (t >= o) ? sh[t - o] : 0;
        __syncthreads();
        sh[t] += x;
        __syncthreads();
    }
    if (idx < NN) g_wpos[idx] = sh[t];
    if (t == 1023) g_btot[blockIdx.x] = sh[1023];
}
__global__ void scan2() {
    __shared__ int sh[64];
    int t = threadIdx.x;
    int v = (t < SCAN_BLKS) ? g_btot[t] : 0;
    sh[t] = v;
    __syncthreads();
#pragma unroll
    for (int o = 1; o < 64; o <<= 1) {
        int x = (t >= o) ? sh[t - o] : 0;
        __syncthreads();
        sh[t] += x;
        __syncthreads();
    }
    if (t < SCAN_BLKS) g_boff[t] = sh[t] - v;
    if (t == SCAN_BLKS - 1) g_rowptr[NN] = sh[t];
}
__global__ void scan3() {
    int idx = blockIdx.x * blockDim.x + threadIdx.x;
    if (idx >= NN) return;
    int excl = g_boff[idx >> 10] + g_wpos[idx] - g_deg[idx];
    g_rowptr[idx] = excl;
    g_wpos[idx] = excl;
}
__global__ void scatter_kernel(const float* __restrict__ R,
                               const int* __restrict__ src,
                               const int* __restrict__ dst) {
    int e = blockIdx.x * blockDim.x + threadIdx.x;
    if (e >= EE) return;
    int s = src[e], d = dst[e];
    float dx = R[s * 3 + 0] - R[d * 3 + 0];
    float dy = R[s * 3 + 1] - R[d * 3 + 1];
    float dz = R[s * 3 + 2] - R[d * 3 + 2];
    float r = sqrtf(dx * dx + dy * dy + dz * dz);
    int pos = atomicAdd(&g_wpos[d], 1);
    float u = (r < 8.0f) ? r * TBL_SCALE : (float)TBL;
    g_su[pos] = make_float2(u, __int_as_float(s));
}

// ---------------- all-layer table build, 4 rows/block ----------------
__global__ void __launch_bounds__(128) build_tables(const float* __restrict__ off,
                                                    const float* __restrict__ wid,
                                                    const float* __restrict__ fw1,
                                                    const float* __restrict__ fb1,
                                                    const float* __restrict__ fw2,
                                                    const float* __restrict__ fb2) {
    int blk = blockIdx.x;
    int l = blk / TBLK;
    int i0 = (blk % TBLK) * TROWS;
    int t = threadIdx.x;
    const float* w1 = fw1 + l * GG * HD;
    const float* b1 = fb1 + l * HD;
    const float* w2 = fw2 + l * HIDN * HD;
    const float* b2 = fb2 + l * HD;
    __shared__ float gs[TROWS][GG];
    __shared__ float hid[TROWS][HIDN];
    if (t < GG) {
        float w = wid[t];
        float coef = -0.5f / (w * w);
        float o = off[t];
#pragma unroll
        for (int q = 0; q < TROWS; q++) {
            float r = (float)(i0 + q) * (8.0f / (float)TBL);
            float dr = r - o;
            gs[q][t] = expf(coef * dr * dr);
        }
    }
    __syncthreads();
    float acc[TROWS];
    float bb = b1[t];
#pragma unroll
    for (int q = 0; q < TROWS; q++) acc[q] = bb;
    for (int g = 0; g < GG; g++) {
        float w = w1[g * HD + t];
#pragma unroll
        for (int q = 0; q < TROWS; q++) acc[q] = fmaf(gs[q][g], w, acc[q]);
    }
#pragma unroll
    for (int q = 0; q < TROWS; q++) hid[q][t] = ssp(acc[q]);
    __syncthreads();
    float bb2 = b2[t];
#pragma unroll
    for (int q = 0; q < TROWS; q++) acc[q] = bb2;
    for (int k = 0; k < HIDN; k++) {
        float w = w2[k * HD + t];
#pragma unroll
        for (int q = 0; q < TROWS; q++) acc[q] = fmaf(hid[q][k], w, acc[q]);
    }
#pragma unroll
    for (int q = 0; q < TROWS; q++) {
        int i = i0 + q;
        if (i > TBL) continue;
        float r = (float)i * (8.0f / (float)TBL);
        float C = (r < 8.0f) ? 0.5f * (cosf(r * 0.39269908169872414f) + 1.0f) : 0.0f;
        float v = acc[q] * C;
        if (i == TBL) v = 0.f;
        g_Tn[(l * (TBL + 1) + i) * HD + t] = __float2half(v);
    }
}

// ---------------- pre phase macro (32 nodes in xs[32*65]) ----------------
#define PRE_PHASE(fcw, al, ar)                                                     \
    {                                                                              \
        int nA = t & 15, nB2 = nA + 16, cg = t >> 4;                               \
        float aA[8], aB[8];                                                        \
        _Pragma("unroll")                                                          \
        for (int j = 0; j < 8; j++) { aA[j] = 0.f; aB[j] = 0.f; }                  \
        const float4* W4 = (const float4*)(fcw);                                   \
        _Pragma("unroll 4")                                                        \
        for (int k = 0; k < 64; k++) {                                             \
            float xA = xs[nA * 65 + k];                                            \
            float xB = xs[nB2 * 65 + k];                                           \
            float4 wa = W4[k * 32 + cg * 2];                                       \
            float4 wb = W4[k * 32 + cg * 2 + 1];                                   \
            aA[0] = fmaf(xA, wa.x, aA[0]); aB[0] = fmaf(xB, wa.x, aB[0]);          \
            aA[1] = fmaf(xA, wa.y, aA[1]); aB[1] = fmaf(xB, wa.y, aB[1]);          \
            aA[2] = fmaf(xA, wa.z, aA[2]); aB[2] = fmaf(xB, wa.z, aB[2]);          \
            aA[3] = fmaf(xA, wa.w, aA[3]); aB[3] = fmaf(xB, wa.w, aB[3]);          \
            aA[4] = fmaf(xA, wb.x, aA[4]); aB[4] = fmaf(xB, wb.x, aB[4]);          \
            aA[5] = fmaf(xA, wb.y, aA[5]); aB[5] = fmaf(xB, wb.y, aB[5]);          \
            aA[6] = fmaf(xA, wb.z, aA[6]); aB[6] = fmaf(xB, wb.z, aB[6]);          \
            aA[7] = fmaf(xA, wb.w, aA[7]); aB[7] = fmaf(xB, wb.w, aB[7]);          \
        }                                                                          \
        bool vA = (n0 + nA) < NN, vB = (n0 + nB2) < NN;                            \
        __half2 hp[4];                                                             \
        hp[0] = __floats2half2_rn(aA[0], aA[1]);                                   \
        hp[1] = __floats2half2_rn(aA[2], aA[3]);                                   \
        hp[2] = __floats2half2_rn(aA[4], aA[5]);                                   \
        hp[3] = __floats2half2_rn(aA[6], aA[7]);                                   \
        if (vA) g_hh[(n0 + nA) * 16 + cg] = *reinterpret_cast<uint4*>(hp);         \
        hp[0] = __floats2half2_rn(aB[0], aB[1]);                                   \
        hp[1] = __floats2half2_rn(aB[2], aB[3]);                                   \
        hp[2] = __floats2half2_rn(aB[4], aB[5]);                                   \
        hp[3] = __floats2half2_rn(aB[6], aB[7]);                                   \
        if (vB) g_hh[(n0 + nB2) * 16 + cg] = *reinterpret_cast<uint4*>(hp);        \
        int head = cg >> 3;                                                        \
        int ca = (cg * 8) & 63;                                                    \
        float4 ala = ((const float4*)(al))[head * 16 + (ca >> 2)];                 \
        float4 alb = ((const float4*)(al))[head * 16 + (ca >> 2) + 1];             \
        float4 ara = ((const float4*)(ar))[head * 16 + (ca >> 2)];                 \
        float4 arb = ((const float4*)(ar))[head * 16 + (ca >> 2) + 1];             \
        float plA = aA[0]*ala.x + aA[1]*ala.y + aA[2]*ala.z + aA[3]*ala.w          \
                  + aA[4]*alb.x + aA[5]*alb.y + aA[6]*alb.z + aA[7]*alb.w;         \
        float prA = aA[0]*ara.x + aA[1]*ara.y + aA[2]*ara.z + aA[3]*ara.w          \
                  + aA[4]*arb.x + aA[5]*arb.y + aA[6]*arb.z + aA[7]*arb.w;         \
        float plB = aB[0]*ala.x + aB[1]*ala.y + aB[2]*ala.z + aB[3]*ala.w          \
                  + aB[4]*alb.x + aB[5]*alb.y + aB[6]*alb.z + aB[7]*alb.w;         \
        float prB = aB[0]*ara.x + aB[1]*ara.y + aB[2]*ara.z + aB[3]*ara.w          \
                  + aB[4]*arb.x + aB[5]*arb.y + aB[6]*arb.z + aB[7]*arb.w;         \
        atomicAdd(&els[nA * 2 + head], plA);                                       \
        atomicAdd(&ers[nA * 2 + head], prA);                                       \
        atomicAdd(&els[nB2 * 2 + head], plB);                                      \
        atomicAdd(&ers[nB2 * 2 + head], prB);                                      \
        __syncthreads();                                                           \
        if (t < 64 && (n0 + (t >> 1)) < NN) {                                      \
            g_el[n0 * 2 + t] = els[t];                                             \
            g_er[n0 * 2 + t] = ers[t];                                             \
        }                                                                          \
    }

// ---------------- layer 0: embed + pre ----------------
__global__ void __launch_bounds__(256) pre_first(const int* __restrict__ Z,
                                                 const float* __restrict__ emb,
                                                 const float* __restrict__ fcw,
                                                 const float* __restrict__ al,
                                                 const float* __restrict__ ar) {
    int n0 = blockIdx.x * 32;
    int t = threadIdx.x;
    __shared__ float xs[32 * 65];
    __shared__ float els[64], ers[64];
    for (int i = t; i < 32 * 64; i += 256) {
        int node = n0 + (i >> 6);
        float v = 0.f;
        if (node < NN) {
            v = emb[Z[node] * DD + (i & 63)];
            g_x[node * DD + (i & 63)] = v;
        }
        xs[(i >> 6) * 65 + (i & 63)] = v;
    }
    if (t < 64) { els[t] = 0.f; ers[t] = 0.f; }
    __syncthreads();
    PRE_PHASE(fcw, al, ar)
}

// ---------------- gather: warp/node, shfl staging, 2-edge unroll ----------------
__global__ void __launch_bounds__(256) gather_v(int l) {
    const __half* Tp = g_Tn + (size_t)l * (TBL + 1) * HD;
    int wid = threadIdx.x >> 5, lane = threadIdx.x & 31;
    int n = blockIdx.x * 8 + wid;
    if (n >= NN) return;
    int beg = g_rowptr[n], end = g_rowptr[n + 1];
    float2 er = ((const float2*)g_er)[n];
    float a0 = 0.f, a1 = 0.f, a2 = 0.f, a3 = 0.f, exs = 0.f;
    const __half* hh = (const __half*)g_hh;
    for (int base = beg; base < end; base += 32) {
        int cnt = min(32, end - base);
        float u = 0.f, e0 = 0.f, e1 = 0.f;
        int s = 0;
        if (lane < cnt) {
            float2 su = g_su[base + lane];
            u = su.x;
            s = __float_as_int(su.y);
            float2 el = ((const float2*)g_el)[s];
            float ev0 = el.x + er.x; ev0 = ev0 > 0.f ? ev0 : 0.2f * ev0;
            float ev1 = el.y + er.y; ev1 = ev1 > 0.f ? ev1 : 0.2f * ev1;
            e0 = __expf(ev0);
            e1 = __expf(ev1);
        }
        int c = 0;
        for (; c + 2 <= cnt; c += 2) {
            float uc0 = __shfl_sync(0xffffffffu, u, c);
            int   sc0 = __shfl_sync(0xffffffffu, s, c);
            float p00 = __shfl_sync(0xffffffffu, e0, c);
            float p01 = __shfl_sync(0xffffffffu, e1, c);
            float uc1 = __shfl_sync(0xffffffffu, u, c + 1);
            int   sc1 = __shfl_sync(0xffffffffu, s, c + 1);
            float p10 = __shfl_sync(0xffffffffu, e0, c + 1);
            float p11 = __shfl_sync(0xffffffffu, e1, c + 1);
            int i0 = (int)(uc0 + 0.5f);
            int i1 = (int)(uc1 + 0.5f);
            uint2 tw0 = *((const uint2*)(Tp + i0 * HD) + lane);
            uint2 hw0 = *((const uint2*)(hh + sc0 * HD) + lane);
            uint2 tw1 = *((const uint2*)(Tp + i1 * HD) + lane);
            uint2 hw1 = *((const uint2*)(hh + sc1 * HD) + lane);
            float ex0 = (lane < 16) ? p00 : p01;
            float ex1 = (lane < 16) ? p10 : p11;
            __half2 q0 = __hmul2(*(__half2*)&tw0.x, *(__half2*)&hw0.x);
            __half2 q1 = __hmul2(*(__half2*)&tw0.y, *(__half2*)&hw0.y);
            float2 f0 = __half22float2(q0);
            float2 f1 = __half22float2(q1);
            a0 = fmaf(f0.x, ex0, a0);
            a1 = fmaf(f0.y, ex0, a1);
            a2 = fmaf(f1.x, ex0, a2);
            a3 = fmaf(f1.y, ex0, a3);
            __half2 q2 = __hmul2(*(__half2*)&tw1.x, *(__half2*)&hw1.x);
            __half2 q3 = __hmul2(*(__half2*)&tw1.y, *(__half2*)&hw1.y);
            float2 f2 = __half22float2(q2);
            float2 f3 = __half22float2(q3);
            a0 = fmaf(f2.x, ex1, a0);
            a1 = fmaf(f2.y, ex1, a1);
            a2 = fmaf(f3.x, ex1, a2);
            a3 = fmaf(f3.y, ex1, a3);
            exs += ex0 + ex1;
        }
        if (c < cnt) {
            float uc = __shfl_sync(0xffffffffu, u, c);
            int   sc = __shfl_sync(0xffffffffu, s, c);
            float p0 = __shfl_sync(0xffffffffu, e0, c);
            float p1 = __shfl_sync(0xffffffffu, e1, c);
            int i = (int)(uc + 0.5f);
            uint2 tw = *((const uint2*)(Tp + i * HD) + lane);
            uint2 hw = *((const uint2*)(hh + sc * HD) + lane);
            float ex = (lane < 16) ? p0 : p1;
            __half2 q0 = __hmul2(*(__half2*)&tw.x, *(__half2*)&hw.x);
            __half2 q1 = __hmul2(*(__half2*)&tw.y, *(__half2*)&hw.y);
            float2 f0 = __half22float2(q0);
            float2 f1 = __half22float2(q1);
            a0 = fmaf(f0.x, ex, a0);
            a1 = fmaf(f0.y, ex, a1);
            a2 = fmaf(f1.x, ex, a2);
            a3 = fmaf(f1.y, ex, a3);
            exs += ex;
        }
    }
    float inv = (exs > 0.f) ? 1.0f / exs : 0.f;
    float4 o;
    o.x = ssp(a0 * inv);
    o.y = ssp(a1 * inv);
    o.z = ssp(a2 * inv);
    o.w = ssp(a3 * inv);
    ((float4*)g_v)[n * 32 + lane] = o;
}

// ---------------- fused: mlp(layer l) + pre(layer l+1) ----------------
__global__ void __launch_bounds__(256) mlp_pre(const float* __restrict__ m1,
                                               const float* __restrict__ mb1,
                                               const float* __restrict__ m2,
                                               const float* __restrict__ mb2,
                                               const float* __restrict__ fcw,
                                               const float* __restrict__ al,
                                               const float* __restrict__ ar) {
    int n0 = blockIdx.x * 32;
    int t = threadIdx.x;
    __shared__ float vs[32 * 129];
    __shared__ float t1s[32 * 65];
    __shared__ float xs[32 * 65];
    __shared__ float els[64], ers[64];
    for (int i = t; i < 32 * 128; i += 256) {
        int node = n0 + (i >> 7);
        vs[(i >> 7) * 129 + (i & 127)] = (node < NN) ? g_v[node * 128 + (i & 127)] : 0.f;
    }
    if (t < 64) { els[t] = 0.f; ers[t] = 0.f; }
    __syncthreads();
    {
        int nA = t & 15, nB2 = nA + 16, cg = t >> 4;
        float aA0 = 0.f, aA1 = 0.f, aA2 = 0.f, aA3 = 0.f;
        float aB0 = 0.f, aB1 = 0.f, aB2 = 0.f, aB3 = 0.f;
        const float4* M1 = (const float4*)m1;
#pragma unroll 4
        for (int k = 0; k < 128; k++) {
            float xA = vs[nA * 129 + k];
            float xB = vs[nB2 * 129 + k];
            float4 w = M1[k * 16 + cg];
            aA0 = fmaf(xA, w.x, aA0); aB0 = fmaf(xB, w.x, aB0);
            aA1 = fmaf(xA, w.y, aA1); aB1 = fmaf(xB, w.y, aB1);
            aA2 = fmaf(xA, w.z, aA2); aB2 = fmaf(xB, w.z, aB2);
            aA3 = fmaf(xA, w.w, aA3); aB3 = fmaf(xB, w.w, aB3);
        }
        float4 b14 = ((const float4*)mb1)[cg];
        t1s[nA * 65 + cg * 4 + 0] = ssp(aA0 + b14.x);
        t1s[nA * 65 + cg * 4 + 1] = ssp(aA1 + b14.y);
        t1s[nA * 65 + cg * 4 + 2] = ssp(aA2 + b14.z);
        t1s[nA * 65 + cg * 4 + 3] = ssp(aA3 + b14.w);
        t1s[nB2 * 65 + cg * 4 + 0] = ssp(aB0 + b14.x);
        t1s[nB2 * 65 + cg * 4 + 1] = ssp(aB1 + b14.y);
        t1s[nB2 * 65 + cg * 4 + 2] = ssp(aB2 + b14.z);
        t1s[nB2 * 65 + cg * 4 + 3] = ssp(aB3 + b14.w);
        __syncthreads();
        aA0 = aA1 = aA2 = aA3 = 0.f;
        aB0 = aB1 = aB2 = aB3 = 0.f;
        const float4* M2 = (const float4*)m2;
#pragma unroll 4
        for (int k = 0; k < 64; k++) {
            float xA = t1s[nA * 65 + k];
            float xB = t1s[nB2 * 65 + k];
            float4 w = M2[k * 16 + cg];
            aA0 = fmaf(xA, w.x, aA0); aB0 = fmaf(xB, w.x, aB0);
            aA1 = fmaf(xA, w.y, aA1); aB1 = fmaf(xB, w.y, aB1);
            aA2 = fmaf(xA, w.z, aA2); aB2 = fmaf(xB, w.z, aB2);
            aA3 = fmaf(xA, w.w, aA3); aB3 = fmaf(xB, w.w, aB3);
        }
        float4 b24 = ((const float4*)mb2)[cg];
        bool vA = (n0 + nA) < NN, vB = (n0 + nB2) < NN;
        float4 xA4 = make_float4(0.f, 0.f, 0.f, 0.f);
        float4 xB4 = make_float4(0.f, 0.f, 0.f, 0.f);
        if (vA) xA4 = ((float4*)g_x)[(n0 + nA) * 16 + cg];
        if (vB) xB4 = ((float4*)g_x)[(n0 + nB2) * 16 + cg];
        xA4.x += aA0 + b24.x; xA4.y += aA1 + b24.y;
        xA4.z += aA2 + b24.z; xA4.w += aA3 + b24.w;
        xB4.x += aB0 + b24.x; xB4.y += aB1 + b24.y;
        xB4.z += aB2 + b24.z; xB4.w += aB3 + b24.w;
        if (vA) ((float4*)g_x)[(n0 + nA) * 16 + cg] = xA4;
        if (vB) ((float4*)g_x)[(n0 + nB2) * 16 + cg] = xB4;
        xs[nA * 65 + cg * 4 + 0] = xA4.x;
        xs[nA * 65 + cg * 4 + 1] = xA4.y;
        xs[nA * 65 + cg * 4 + 2] = xA4.z;
        xs[nA * 65 + cg * 4 + 3] = xA4.w;
        xs[nB2 * 65 + cg * 4 + 0] = xB4.x;
        xs[nB2 * 65 + cg * 4 + 1] = xB4.y;
        xs[nB2 * 65 + cg * 4 + 2] = xB4.z;
        xs[nB2 * 65 + cg * 4 + 3] = xB4.w;
    }
    __syncthreads();
    PRE_PHASE(fcw, al, ar)
}

// ---------------- fused: mlp(last layer) + output head ----------------
__global__ void zero_out(float* out) {
    if (threadIdx.x < BB) out[threadIdx.x] = 0.f;
}

__global__ void __launch_bounds__(256) mlp_out(const float* __restrict__ m1,
                                               const float* __restrict__ mb1,
                                               const float* __restrict__ m2,
                                               const float* __restrict__ mb2,
                                               const float* __restrict__ w1o,
                                               const float* __restrict__ b1o,
                                               const float* __restrict__ w2o,
                                               const float* __restrict__ b2o,
                                               const int* __restrict__ gid,
                                               float* __restrict__ out) {
    int n0 = blockIdx.x * 16;          // 3125 blocks exact
    int t = threadIdx.x;
    __shared__ float vs[16 * 129];
    __shared__ float t1s[16 * 65];
    __shared__ float xs[16 * 65];
    __shared__ float sred[16][17];
    for (int i = t; i < 16 * 128; i += 256)
        vs[(i >> 7) * 129 + (i & 127)] = g_v[n0 * 128 + i];
    __syncthreads();
    int n = t & 15, cg = t >> 4;
    {
        float a0 = 0.f, a1 = 0.f, a2 = 0.f, a3 = 0.f;
        const float4* M1 = (const float4*)m1;
#pragma unroll 4
        for (int k = 0; k < 128; k++) {
            float xv = vs[n * 129 + k];
            float4 w = M1[k * 16 + cg];
            a0 = fmaf(xv, w.x, a0);
            a1 = fmaf(xv, w.y, a1);
            a2 = fmaf(xv, w.z, a2);
            a3 = fmaf(xv, w.w, a3);
        }
        float4 b14 = ((const float4*)mb1)[cg];
        t1s[n * 65 + cg * 4 + 0] = ssp(a0 + b14.x);
        t1s[n * 65 + cg * 4 + 1] = ssp(a1 + b14.y);
        t1s[n * 65 + cg * 4 + 2] = ssp(a2 + b14.z);
        t1s[n * 65 + cg * 4 + 3] = ssp(a3 + b14.w);
        __syncthreads();
        a0 = a1 = a2 = a3 = 0.f;
        const float4* M2 = (const float4*)m2;
#pragma unroll 4
        for (int k = 0; k < 64; k++) {
            float xv = t1s[n * 65 + k];
            float4 w = M2[k * 16 + cg];
            a0 = fmaf(xv, w.x, a0);
            a1 = fmaf(xv, w.y, a1);
            a2 = fmaf(xv, w.z, a2);
            a3 = fmaf(xv, w.w, a3);
        }
        float4 b24 = ((const float4*)mb2)[cg];
        float4 x4 = ((const float4*)g_x)[(n0 + n) * 16 + cg];
        xs[n * 65 + cg * 4 + 0] = x4.x + a0 + b24.x;
        xs[n * 65 + cg * 4 + 1] = x4.y + a1 + b24.y;
        xs[n * 65 + cg * 4 + 2] = x4.z + a2 + b24.z;
        xs[n * 65 + cg * 4 + 3] = x4.w + a3 + b24.w;
    }
    __syncthreads();
    float acc[8];
#pragma unroll
    for (int j = 0; j < 8; j++) acc[j] = 0.f;
    const float4* W4 = (const float4*)w1o;
#pragma unroll 4
    for (int k = 0; k < 64; k++) {
        float xv = xs[n * 65 + k];
        float4 wa = W4[k * 32 + cg * 2];
        float4 wb = W4[k * 32 + cg * 2 + 1];
        acc[0] = fmaf(xv, wa.x, acc[0]);
        acc[1] = fmaf(xv, wa.y, acc[1]);
        acc[2] = fmaf(xv, wa.z, acc[2]);
        acc[3] = fmaf(xv, wa.w, acc[3]);
        acc[4] = fmaf(xv, wb.x, acc[4]);
        acc[5] = fmaf(xv, wb.y, acc[5]);
        acc[6] = fmaf(xv, wb.z, acc[6]);
        acc[7] = fmaf(xv, wb.w, acc[7]);
    }
    float4 b1a = ((const float4*)b1o)[cg * 2];
    float4 b1b = ((const float4*)b1o)[cg * 2 + 1];
    float4 w2a = ((const float4*)w2o)[cg * 2];
    float4 w2b = ((const float4*)w2o)[cg * 2 + 1];
    float p = ssp(acc[0] + b1a.x) * w2a.x + ssp(acc[1] + b1a.y) * w2a.y
            + ssp(acc[2] + b1a.z) * w2a.z + ssp(acc[3] + b1a.w) * w2a.w
            + ssp(acc[4] + b1b.x) * w2b.x + ssp(acc[5] + b1b.y) * w2b.y
            + ssp(acc[6] + b1b.z) * w2b.z + ssp(acc[7] + b1b.w) * w2b.w;
    sred[cg][n] = p;
    __syncthreads();
    if (t < 16) {
        float s = b2o[0];
#pragma unroll
        for (int c = 0; c < 16; c++) s += sred[c][t];
        atomicAdd(&out[gid[n0 + t]], s);
    }
}

extern "C" void kernel_launch(void* const* d_in, const int* in_sizes, int n_in,
                              void* d_out, int out_size) {
    const float* R    = (const float*)d_in[0];
    const int*   Z    = (const int*)d_in[1];
    const int*   src  = (const int*)d_in[2];
    const int*   dst  = (const int*)d_in[3];
    const int*   gid  = (const int*)d_in[4];
    const float* emb  = (const float*)d_in[5];
    const float* off  = (const float*)d_in[6];
    const float* wid  = (const float*)d_in[7];
    const float* fcw  = (const float*)d_in[8];
    const float* al   = (const float*)d_in[9];
    const float* ar   = (const float*)d_in[10];
    const float* fw1  = (const float*)d_in[11];
    const float* fb1  = (const float*)d_in[12];
    const float* fw2  = (const float*)d_in[13];
    const float* fb2  = (const float*)d_in[14];
    const float* m1   = (const float*)d_in[15];
    const float* mb1  = (const float*)d_in[16];
    const float* m2   = (const float*)d_in[17];
    const float* mb2  = (const float*)d_in[18];
    const float* ow1  = (const float*)d_in[19];
    const float* ob1  = (const float*)d_in[20];
    const float* ow2  = (const float*)d_in[21];
    const float* ob2  = (const float*)d_in[22];
    float* out = (float*)d_out;

    zero_out<<<1, 64>>>(out);
    zero_deg<<<(NN + 255) / 256, 256>>>();
    count_deg<<<(EE + 255) / 256, 256>>>(dst);
    scan1<<<SCAN_BLKS, 1024>>>();
    scan2<<<1, 64>>>();
    scan3<<<(NN + 255) / 256, 256>>>();
    scatter_kernel<<<(EE + 255) / 256, 256>>>(R, src, dst);
    build_tables<<<LLAYERS * TBLK, 128>>>(off, wid, fw1, fb1, fw2, fb2);

    pre_first<<<(NN + 31) / 32, 256>>>(Z, emb, fcw, al, ar);
    gather_v<<<(NN + 7) / 8, 256>>>(0);
    mlp_pre<<<(NN + 31) / 32, 256>>>(m1, mb1, m2, mb2,
                                     fcw + 1 * DD * HD, al + 1 * 2 * DD, ar + 1 * 2 * DD);
    gather_v<<<(NN + 7) / 8, 256>>>(1);
    mlp_pre<<<(NN + 31) / 32, 256>>>(m1 + 1 * HD * DD, mb1 + 1 * DD, m2 + 1 * DD * DD, mb2 + 1 * DD,
                                     fcw + 2 * DD * HD, al + 2 * 2 * DD, ar + 2 * 2 * DD);
    gather_v<<<(NN + 7) / 8, 256>>>(2);
    mlp_out<<<NN / 16, 256>>>(m1 + 2 * HD * DD, mb1 + 2 * DD, m2 + 2 * DD * DD, mb2 + 2 * DD,
                              ow1, ob1, ow2, ob2, gid, out);
}